// round 9
// baseline (speedup 1.0000x reference)
#include <cuda_runtime.h>
#include <cstdint>

// BLOCK=64, IB=2: 1024 blocks AND 2 dependency chains per thread.
// Fused decoder M = Wg2 @ Wd1 computed per-block in smem during init.
// Per-batch FP math identical to rounds 5-8 (rel_err preservation).
// Output layout: [recon (nb*8)] [lat (nb*16)] [A (nb*64)]

constexpr int NN = 8;
constexpr int BLOCK = 64;
constexpr int IB = 2;

using u64 = unsigned long long;

__device__ __forceinline__ u64 pk(float lo, float hi) {
    u64 r; asm("mov.b64 %0, {%1,%2};" : "=l"(r) : "f"(lo), "f"(hi)); return r;
}
__device__ __forceinline__ void upk(u64 v, float& lo, float& hi) {
    asm("mov.b64 {%0,%1}, %2;" : "=f"(lo), "=f"(hi) : "l"(v));
}
__device__ __forceinline__ u64 fma2(u64 a, u64 b, u64 c) {
    u64 d; asm("fma.rn.f32x2 %0, %1, %2, %3;" : "=l"(d) : "l"(a), "l"(b), "l"(c)); return d;
}
__device__ __forceinline__ u64 add2(u64 a, u64 b) {
    u64 d; asm("add.rn.f32x2 %0, %1, %2;" : "=l"(d) : "l"(a), "l"(b)); return d;
}
__device__ __forceinline__ u64 dup2(float v) { return pk(v, v); }
__device__ __forceinline__ u64 relu2(u64 v) {
    float a, b; upk(v, a, b);
    return pk(fmaxf(a, 0.0f), fmaxf(b, 0.0f));
}

__device__ __forceinline__ constexpr int PIDX(int i, int j) { // i<j, 0..27
    return i * 7 - (i * (i - 1)) / 2 + (j - i - 1);
}

__global__ void __launch_bounds__(BLOCK, 8)
gae_kernel(const float* __restrict__ x, const float* __restrict__ noise,
           const float* __restrict__ We1, const float* __restrict__ be1,
           const float* __restrict__ We2, const float* __restrict__ be2,
           const float* __restrict__ Wg1, const float* __restrict__ bg1,
           const float* __restrict__ Wg2, const float* __restrict__ bg2,
           const float* __restrict__ Wd1, const float* __restrict__ bd1,
           const float* __restrict__ Wd2, const float* __restrict__ bd2,
           float* __restrict__ out, int nb)
{
    __shared__ float4 sencWq[64];       // (w1,w1, e0,e0) duplicated pairs
    __shared__ float2 sencE1[64];       // (e1,e1)
    __shared__ float4 sencC[128];       // [k][2]: c_i = fmaf(i, w2, be1)
    __shared__ float4 sWg1q[32];        // (g0,g0, g1,g1)
    __shared__ float2 sWg1b[32];        // (bg,bg)
    __shared__ float4 sMT4[64 * 8];     // fused decoder M[e][c], c contiguous
    __shared__ float2 scw[64];          // (bg2@Wd1 + bd1, Wd2[e][1])
    __shared__ float  sbd2v;
    __shared__ float  sWg2T[32 * 33];   // Wg2 transposed, padded (staging)
    __shared__ float4 sWd1s4[32 * 16];  // Wd1 staged: [d][pp] = Wd1[d][4pp..4pp+3]

    const int t = threadIdx.x;          // 0..63
    const u64 z2 = pk(0.0f, 0.0f);

    // ---- stage raw weights (all 64 threads) ----
    {
        float w1 = We1[64 + t];
        float w2 = We1[128 + t];
        float be = be1[t];
        float e0 = We2[2 * t], e1 = We2[2 * t + 1];
        sencWq[t] = make_float4(w1, w1, e0, e0);
        sencE1[t] = make_float2(e1, e1);
        float c[8];
        #pragma unroll
        for (int i = 0; i < 8; i++) c[i] = fmaf((float)i, w2, be);
        sencC[2 * t]     = make_float4(c[0], c[1], c[2], c[3]);
        sencC[2 * t + 1] = make_float4(c[4], c[5], c[6], c[7]);
    }
    if (t < 32) {
        float g0 = Wg1[t], g1 = Wg1[32 + t], bg = bg1[t];
        sWg1q[t] = make_float4(g0, g0, g1, g1);
        sWg1b[t] = make_float2(bg, bg);
    }
    for (int idx = t; idx < 1024; idx += BLOCK) {
        int c = idx >> 5, d = idx & 31;
        sWg2T[d * 33 + c] = Wg2[idx];          // coalesced LDG, pad-33 STS
    }
    for (int idx = t; idx < 512; idx += BLOCK) {
        sWd1s4[idx] = *(const float4*)&Wd1[4 * idx];   // idx = d*16 + pp
    }
    if (t == 0) sbd2v = bd2[1];
    __syncthreads();

    // ---- fused decoder weights: M[e][c] = sum_d Wg2[c][d]*Wd1[d][e] ----
    // Each thread: column c = t&31, e-pair range p in [half*16, half*16+16).
    // Per-acc d-ordered fma2 chain identical to prior rounds (same M bits).
    {
        int c = t & 31, half = t >> 5;
        u64 acc[16];
        #pragma unroll
        for (int k = 0; k < 16; k++) acc[k] = z2;
        for (int d = 0; d < 32; d++) {
            u64 ad = dup2(sWg2T[d * 33 + c]);
            const float4* fb = &sWd1s4[d * 16 + half * 8];
            #pragma unroll
            for (int q = 0; q < 8; q++) {
                float4 f = fb[q];
                acc[2 * q]     = fma2(ad, pk(f.x, f.y), acc[2 * q]);
                acc[2 * q + 1] = fma2(ad, pk(f.z, f.w), acc[2 * q + 1]);
            }
        }
        #pragma unroll
        for (int k = 0; k < 16; k++) {
            int p = half * 16 + k;
            float mlo, mhi; upk(acc[k], mlo, mhi);
            ((float*)sMT4)[(2 * p)     * 32 + c] = mlo;
            ((float*)sMT4)[(2 * p + 1) * 32 + c] = mhi;
        }
    }
    {
        float ce = bd1[t];
        int pp = t >> 2, r = t & 3;
        #pragma unroll
        for (int d = 0; d < 32; d++) {
            float4 w = sWd1s4[d * 16 + pp];
            float vv = (r & 2) ? ((r & 1) ? w.w : w.z) : ((r & 1) ? w.y : w.x);
            ce = fmaf(bg2[d], vv, ce);
        }
        scw[t] = make_float2(ce, Wd2[t * 3 + 1]);
    }
    __syncthreads();

    const int b0 = blockIdx.x * (BLOCK * IB) + t;

    float* out_recon = out;
    float* out_lat   = out + (size_t)nb * 8;
    float* out_A     = out + (size_t)nb * 24;

    // ---------------- P0: load x ----------------
    u64 x2[IB][4];
    #pragma unroll
    for (int u = 0; u < IB; u++) {
        int b = b0 + u * BLOCK;
        if (b < nb) {
            const float4* xp = (const float4*)(x + (size_t)b * 8);
            float4 a = xp[0], c = xp[1];
            x2[u][0] = pk(a.x, a.y); x2[u][1] = pk(a.z, a.w);
            x2[u][2] = pk(c.x, c.y); x2[u][3] = pk(c.z, c.w);
        } else {
            #pragma unroll
            for (int q = 0; q < 4; q++) x2[u][q] = 0ull;
        }
    }

    // ---------------- P1: encoder ----------------
    u64 l0p[IB][4], l1p[IB][4];
    #pragma unroll
    for (int u = 0; u < IB; u++)
        #pragma unroll
        for (int q = 0; q < 4; q++) { l0p[u][q] = z2; l1p[u][q] = z2; }

    #pragma unroll 2
    for (int k = 0; k < 64; k++) {
        float4 wq = sencWq[k];
        float2 e1 = sencE1[k];
        float4 ca = sencC[2 * k];
        float4 cb = sencC[2 * k + 1];
        u64 w1d = pk(wq.x, wq.y), e0d = pk(wq.z, wq.w), e1d = pk(e1.x, e1.y);
        u64 c2[4] = { pk(ca.x, ca.y), pk(ca.z, ca.w),
                      pk(cb.x, cb.y), pk(cb.z, cb.w) };
        #pragma unroll
        for (int u = 0; u < IB; u++) {
            #pragma unroll
            for (int q = 0; q < 4; q++) {
                u64 h = relu2(fma2(x2[u][q], w1d, c2[q]));
                l0p[u][q] = fma2(h, e0d, l0p[u][q]);
                l1p[u][q] = fma2(h, e1d, l1p[u][q]);
            }
        }
    }

    // ---------------- P2/P3: stats, noise, px/py, lat store ----------------
    float px[IB][8], py[IB][8];
    #pragma unroll
    for (int u = 0; u < IB; u++) {
        int b = b0 + u * BLOCK;
        float l0[8], l1[8];
        #pragma unroll
        for (int q = 0; q < 4; q++) {
            upk(l0p[u][q], l0[2 * q], l0[2 * q + 1]);
            upk(l1p[u][q], l1[2 * q], l1[2 * q + 1]);
        }
        float mu0 = 0.0f, mu1 = 0.0f;
        #pragma unroll
        for (int i = 0; i < 8; i++) { mu0 += l0[i]; mu1 += l1[i]; }
        mu0 *= 0.125f; mu1 *= 0.125f;

        float v0 = 0.0f, v1 = 0.0f;
        #pragma unroll
        for (int i = 0; i < 8; i++) {
            float c0 = l0[i] - mu0, c1 = l1[i] - mu1;
            v0 += c0 * c0; v1 += c1 * c1;
        }
        float sc0 = 3.0f / (sqrtf(v0 * (1.0f / 7.0f)) + 1e-8f);
        float sc1 = 3.0f / (sqrtf(v1 * (1.0f / 7.0f)) + 1e-8f);

        float nz[16];
        if (b < nb) {
            const float4* np = (const float4*)(noise + (size_t)b * 16);
            float4 q0 = np[0], q1 = np[1], q2 = np[2], q3 = np[3];
            nz[0]=q0.x; nz[1]=q0.y; nz[2]=q0.z; nz[3]=q0.w;
            nz[4]=q1.x; nz[5]=q1.y; nz[6]=q1.z; nz[7]=q1.w;
            nz[8]=q2.x; nz[9]=q2.y; nz[10]=q2.z; nz[11]=q2.w;
            nz[12]=q3.x; nz[13]=q3.y; nz[14]=q3.z; nz[15]=q3.w;
        } else {
            #pragma unroll
            for (int i = 0; i < 16; i++) nz[i] = 0.0f;
        }
        #pragma unroll
        for (int i = 0; i < 8; i++) {
            px[u][i] = ((l0[i] - mu0) * sc0) + nz[2 * i]     * 0.05f;
            py[u][i] = ((l1[i] - mu1) * sc1) + nz[2 * i + 1] * 0.05f;
        }
        if (b < nb) {
            float4* lp = (float4*)(out_lat + (size_t)b * 16);
            #pragma unroll
            for (int q = 0; q < 4; q++) {
                float4 o;
                o.x = px[u][2 * q];     o.y = py[u][2 * q];
                o.z = px[u][2 * q + 1]; o.w = py[u][2 * q + 1];
                lp[q] = o;
            }
        }
    }

    // ---------------- P4: Gabriel graph (expression-identical) ----------------
    unsigned am[IB];
    int deg[IB][8];
    #pragma unroll
    for (int u = 0; u < IB; u++) {
        am[u] = 0;
        #pragma unroll
        for (int i = 0; i < 8; i++) deg[u][i] = 1;
    }

    #pragma unroll
    for (int i = 0; i < 8; i++) {
        #pragma unroll
        for (int j = i + 1; j < 8; j++) {
            #pragma unroll
            for (int u = 0; u < IB; u++) {
                float mx = (px[u][i] + px[u][j]) * 0.5f;
                float my = (py[u][i] + py[u][j]) * 0.5f;
                float dx = px[u][i] - mx, dy = py[u][i] - my;
                float r2 = dx * dx + dy * dy;
                float mind2 = 3.402823e38f;
                #pragma unroll
                for (int k = 0; k < 8; k++) {
                    if (k != i && k != j) {
                        float ax = px[u][k] - mx, ay = py[u][k] - my;
                        mind2 = fminf(mind2, ax * ax + ay * ay);
                    }
                }
                if (mind2 >= r2) {
                    am[u] |= (1u << PIDX(i, j));
                    deg[u][i]++; deg[u][j]++;
                }
            }
        }
    }

    float dinv[IB][8];
    #pragma unroll
    for (int u = 0; u < IB; u++)
        #pragma unroll
        for (int i = 0; i < 8; i++) dinv[u][i] = rsqrtf((float)deg[u][i]);

    // A output (raw 0/1 adjacency, zero diagonal)
    #pragma unroll
    for (int u = 0; u < IB; u++) {
        int b = b0 + u * BLOCK;
        if (b >= nb) continue;
        float4* ap = (float4*)(out_A + (size_t)b * 64);
        #pragma unroll
        for (int i = 0; i < 8; i++) {
            float row[8];
            #pragma unroll
            for (int j = 0; j < 8; j++) {
                if (i == j) row[j] = 0.0f;
                else {
                    int p = (i < j) ? PIDX(i, j) : PIDX(j, i);
                    row[j] = ((am[u] >> p) & 1u) ? 1.0f : 0.0f;
                }
            }
            ap[2 * i]     = make_float4(row[0], row[1], row[2], row[3]);
            ap[2 * i + 1] = make_float4(row[4], row[5], row[6], row[7]);
        }
    }

    // ---------------- P5: qx/qy/s via wx = dinv*px (predicated adds) --------
    u64 qx2[IB][4], qy2[IB][4], s2[IB][4];
    {
        float wx[IB][8], wy[IB][8];
        #pragma unroll
        for (int u = 0; u < IB; u++)
            #pragma unroll
            for (int j = 0; j < 8; j++) {
                wx[u][j] = dinv[u][j] * px[u][j];
                wy[u][j] = dinv[u][j] * py[u][j];
            }

        float tqx[IB], tqy[IB], ts[IB];
        #pragma unroll
        for (int n = 0; n < 8; n++) {
            #pragma unroll
            for (int u = 0; u < IB; u++) {
                float tx = wx[u][n], ty = wy[u][n], td = dinv[u][n];
                #pragma unroll
                for (int j = 0; j < 8; j++) {
                    if (j == n) continue;
                    int p = (n < j) ? PIDX(n, j) : PIDX(j, n);
                    bool adj = (am[u] >> p) & 1u;
                    if (adj) { tx += wx[u][j]; ty += wy[u][j]; td += dinv[u][j]; }
                }
                float qxn = dinv[u][n] * tx;
                float qyn = dinv[u][n] * ty;
                float sn  = dinv[u][n] * td * 0.125f;
                if (n & 1) {
                    qx2[u][n >> 1] = pk(tqx[u], qxn);
                    qy2[u][n >> 1] = pk(tqy[u], qyn);
                    s2[u][n >> 1]  = pk(ts[u], sn);
                } else {
                    tqx[u] = qxn; tqy[u] = qyn; ts[u] = sn;
                }
            }
        }
    }

    // ---------------- P6: GCN channel values u_c ----------------
    u64 u2[IB][16];
    {
        float tu[IB];
        #pragma unroll 2
        for (int c = 0; c < 32; c++) {
            float4 g   = sWg1q[c];
            float2 bgp = sWg1b[c];
            u64 g0d = pk(g.x, g.y), g1d = pk(g.z, g.w), bgd = pk(bgp.x, bgp.y);
            #pragma unroll
            for (int u = 0; u < IB; u++) {
                u64 acc2 = z2;
                #pragma unroll
                for (int q = 0; q < 4; q++) {
                    u64 a = fma2(qx2[u][q], g0d, fma2(qy2[u][q], g1d, bgd));
                    acc2 = fma2(s2[u][q], relu2(a), acc2);
                }
                float ua, ub; upk(acc2, ua, ub);
                float uc = ua + ub;
                if (c & 1) u2[u][c >> 1] = pk(tu[u], uc);
                else       tu[u] = uc;
            }
        }
    }

    // ---------------- P7: fused decoder -> recon (streamed M rows) ----------
    float recon[IB];
    #pragma unroll
    for (int u = 0; u < IB; u++) recon[u] = sbd2v;

    #pragma unroll 2
    for (int e = 0; e < 64; e++) {
        const float4* wr = &sMT4[e * 8];
        float2 cw = scw[e];
        u64 accA0 = z2, accB0 = z2, accA1 = z2, accB1 = z2;
        #pragma unroll
        for (int q = 0; q < 8; q++) {
            float4 f = wr[q];
            u64 mA = pk(f.x, f.y), mB = pk(f.z, f.w);
            accA0 = fma2(u2[0][2 * q],     mA, accA0);
            accB0 = fma2(u2[0][2 * q + 1], mB, accB0);
            accA1 = fma2(u2[1][2 * q],     mA, accA1);
            accB1 = fma2(u2[1][2 * q + 1], mB, accB1);
        }
        {
            u64 acc = add2(accA0, accB0);
            float sa, sb; upk(acc, sa, sb);
            float pre = (sa + sb) + cw.x;
            recon[0] = fmaf(fmaxf(pre, 0.0f), cw.y, recon[0]);
        }
        {
            u64 acc = add2(accA1, accB1);
            float sa, sb; upk(acc, sa, sb);
            float pre = (sa + sb) + cw.x;
            recon[1] = fmaf(fmaxf(pre, 0.0f), cw.y, recon[1]);
        }
    }

    #pragma unroll
    for (int u = 0; u < IB; u++) {
        int b = b0 + u * BLOCK;
        if (b >= nb) continue;
        float4 r4 = {recon[u], recon[u], recon[u], recon[u]};
        float4* rp = (float4*)(out_recon + (size_t)b * 8);
        rp[0] = r4;
        rp[1] = r4;
    }
}

extern "C" void kernel_launch(void* const* d_in, const int* in_sizes, int n_in,
                              void* d_out, int out_size)
{
    const float* x     = (const float*)d_in[0];
    const float* noise = (const float*)d_in[1];
    const float* We1   = (const float*)d_in[2];
    const float* be1   = (const float*)d_in[3];
    const float* We2   = (const float*)d_in[4];
    const float* be2   = (const float*)d_in[5];
    const float* Wg1   = (const float*)d_in[6];
    const float* bg1   = (const float*)d_in[7];
    const float* Wg2   = (const float*)d_in[8];
    const float* bg2   = (const float*)d_in[9];
    const float* Wd1   = (const float*)d_in[10];
    const float* bd1   = (const float*)d_in[11];
    const float* Wd2   = (const float*)d_in[12];
    const float* bd2   = (const float*)d_in[13];

    const int nb = in_sizes[0] / NN;
    float* out = (float*)d_out;

    dim3 grid((nb + BLOCK * IB - 1) / (BLOCK * IB));
    gae_kernel<<<grid, BLOCK>>>(x, noise, We1, be1, We2, be2, Wg1, bg1,
                                Wg2, bg2, Wd1, bd1, Wd2, bd2, out, nb);
}

// round 10
// speedup vs baseline: 1.0809x; 1.0809x over previous
#include <cuda_runtime.h>
#include <cstdint>

// R10 = R8 (IB=1, BLOCK=128, fused decoder) + __launch_bounds__(128,7):
// 7 CTA/SM -> 148*7=1036 >= 1024 blocks -> SINGLE WAVE (kills tail wave).
// Per-batch FP math identical to rounds 5-9 (rel_err preservation).
// Output layout: [recon (nb*8)] [lat (nb*16)] [A (nb*64)]

constexpr int NN = 8;
constexpr int BLOCK = 128;

using u64 = unsigned long long;

__device__ __forceinline__ u64 pk(float lo, float hi) {
    u64 r; asm("mov.b64 %0, {%1,%2};" : "=l"(r) : "f"(lo), "f"(hi)); return r;
}
__device__ __forceinline__ void upk(u64 v, float& lo, float& hi) {
    asm("mov.b64 {%0,%1}, %2;" : "=f"(lo), "=f"(hi) : "l"(v));
}
__device__ __forceinline__ u64 fma2(u64 a, u64 b, u64 c) {
    u64 d; asm("fma.rn.f32x2 %0, %1, %2, %3;" : "=l"(d) : "l"(a), "l"(b), "l"(c)); return d;
}
__device__ __forceinline__ u64 add2(u64 a, u64 b) {
    u64 d; asm("add.rn.f32x2 %0, %1, %2;" : "=l"(d) : "l"(a), "l"(b)); return d;
}
__device__ __forceinline__ u64 dup2(float v) { return pk(v, v); }
__device__ __forceinline__ u64 relu2(u64 v) {
    float a, b; upk(v, a, b);
    return pk(fmaxf(a, 0.0f), fmaxf(b, 0.0f));
}

__device__ __forceinline__ constexpr int PIDX(int i, int j) { // i<j, 0..27
    return i * 7 - (i * (i - 1)) / 2 + (j - i - 1);
}

__global__ void __launch_bounds__(BLOCK, 7)
gae_kernel(const float* __restrict__ x, const float* __restrict__ noise,
           const float* __restrict__ We1, const float* __restrict__ be1,
           const float* __restrict__ We2, const float* __restrict__ be2,
           const float* __restrict__ Wg1, const float* __restrict__ bg1,
           const float* __restrict__ Wg2, const float* __restrict__ bg2,
           const float* __restrict__ Wd1, const float* __restrict__ bd1,
           const float* __restrict__ Wd2, const float* __restrict__ bd2,
           float* __restrict__ out, int nb)
{
    __shared__ float4 sencWq[64];       // (w1,w1, e0,e0) duplicated pairs
    __shared__ float2 sencE1[64];       // (e1,e1)
    __shared__ float4 sencC[128];       // [k][2]: c_i = fmaf(i, w2, be1)
    __shared__ float4 sWg1q[32];        // (g0,g0, g1,g1)
    __shared__ float2 sWg1b[32];        // (bg,bg)
    __shared__ float4 sMT4[64 * 8];     // fused decoder M[e][c], c contiguous
    __shared__ float2 scw[64];          // (bg2@Wd1 + bd1, Wd2[e][1])
    __shared__ float  sbd2v;
    __shared__ float  sWg2T[32 * 33];   // Wg2 transposed, padded (staging)
    __shared__ float4 sWd1s4[32 * 16];  // Wd1 staged: [d][pp] = Wd1[d][4pp..4pp+3]

    const int t = threadIdx.x;
    const u64 z2 = pk(0.0f, 0.0f);

    // ---- stage raw weights ----
    if (t < 64) {
        float w1 = We1[64 + t];
        float w2 = We1[128 + t];
        float be = be1[t];
        float e0 = We2[2 * t], e1 = We2[2 * t + 1];
        sencWq[t] = make_float4(w1, w1, e0, e0);
        sencE1[t] = make_float2(e1, e1);
        float c[8];
        #pragma unroll
        for (int i = 0; i < 8; i++) c[i] = fmaf((float)i, w2, be);
        sencC[2 * t]     = make_float4(c[0], c[1], c[2], c[3]);
        sencC[2 * t + 1] = make_float4(c[4], c[5], c[6], c[7]);
    }
    if (t < 32) {
        float g0 = Wg1[t], g1 = Wg1[32 + t], bg = bg1[t];
        sWg1q[t] = make_float4(g0, g0, g1, g1);
        sWg1b[t] = make_float2(bg, bg);
    }
    for (int idx = t; idx < 1024; idx += BLOCK) {
        int c = idx >> 5, d = idx & 31;
        sWg2T[d * 33 + c] = Wg2[idx];          // coalesced LDG, pad-33 STS
    }
    for (int idx = t; idx < 512; idx += BLOCK) {
        sWd1s4[idx] = *(const float4*)&Wd1[4 * idx];   // idx = d*16 + pp
    }
    if (t == 0) sbd2v = bd2[1];
    __syncthreads();

    // ---- fused decoder weights: M[e][c] = sum_d Wg2[c][d]*Wd1[d][e] ----
    {
        int c = t & 31, ep0 = t >> 5;
        u64 acc[8];
        #pragma unroll
        for (int k = 0; k < 8; k++) acc[k] = z2;
        #pragma unroll 2
        for (int d = 0; d < 32; d++) {
            u64 ad = dup2(sWg2T[d * 33 + c]);
            float4 f0 = sWd1s4[d * 16 + ep0 * 4 + 0];
            float4 f1 = sWd1s4[d * 16 + ep0 * 4 + 1];
            float4 f2 = sWd1s4[d * 16 + ep0 * 4 + 2];
            float4 f3 = sWd1s4[d * 16 + ep0 * 4 + 3];
            acc[0] = fma2(ad, pk(f0.x, f0.y), acc[0]);
            acc[1] = fma2(ad, pk(f0.z, f0.w), acc[1]);
            acc[2] = fma2(ad, pk(f1.x, f1.y), acc[2]);
            acc[3] = fma2(ad, pk(f1.z, f1.w), acc[3]);
            acc[4] = fma2(ad, pk(f2.x, f2.y), acc[4]);
            acc[5] = fma2(ad, pk(f2.z, f2.w), acc[5]);
            acc[6] = fma2(ad, pk(f3.x, f3.y), acc[6]);
            acc[7] = fma2(ad, pk(f3.z, f3.w), acc[7]);
        }
        #pragma unroll
        for (int k = 0; k < 8; k++) {
            int p = ep0 * 8 + k;
            float mlo, mhi; upk(acc[k], mlo, mhi);
            ((float*)sMT4)[(2 * p)     * 32 + c] = mlo;
            ((float*)sMT4)[(2 * p + 1) * 32 + c] = mhi;
        }
    }
    if (t < 64) {
        float ce = bd1[t];
        int pp = t >> 2, r = t & 3;
        #pragma unroll
        for (int d = 0; d < 32; d++) {
            float4 w = sWd1s4[d * 16 + pp];
            float vv = (r & 2) ? ((r & 1) ? w.w : w.z) : ((r & 1) ? w.y : w.x);
            ce = fmaf(bg2[d], vv, ce);
        }
        scw[t] = make_float2(ce, Wd2[t * 3 + 1]);
    }
    __syncthreads();

    const int b = blockIdx.x * BLOCK + t;
    if (b >= nb) return;

    float* out_recon = out;
    float* out_lat   = out + (size_t)nb * 8;
    float* out_A     = out + (size_t)nb * 24;

    // ---------------- P0: load x ----------------
    u64 x2[4];
    {
        const float4* xp = (const float4*)(x + (size_t)b * 8);
        float4 a = xp[0], c = xp[1];
        x2[0] = pk(a.x, a.y); x2[1] = pk(a.z, a.w);
        x2[2] = pk(c.x, c.y); x2[3] = pk(c.z, c.w);
    }

    // ---------------- P1: encoder ----------------
    u64 l0p[4], l1p[4];
    #pragma unroll
    for (int q = 0; q < 4; q++) { l0p[q] = z2; l1p[q] = z2; }

    #pragma unroll 2
    for (int k = 0; k < 64; k++) {
        float4 wq = sencWq[k];
        float2 e1 = sencE1[k];
        float4 ca = sencC[2 * k];
        float4 cb = sencC[2 * k + 1];
        u64 w1d = pk(wq.x, wq.y), e0d = pk(wq.z, wq.w), e1d = pk(e1.x, e1.y);
        u64 c2[4] = { pk(ca.x, ca.y), pk(ca.z, ca.w),
                      pk(cb.x, cb.y), pk(cb.z, cb.w) };
        #pragma unroll
        for (int q = 0; q < 4; q++) {
            u64 h = relu2(fma2(x2[q], w1d, c2[q]));
            l0p[q] = fma2(h, e0d, l0p[q]);
            l1p[q] = fma2(h, e1d, l1p[q]);
        }
    }

    // ---------------- P2/P3: stats, noise, px/py, lat store ----------------
    float px[8], py[8];
    {
        float l0[8], l1[8];
        #pragma unroll
        for (int q = 0; q < 4; q++) {
            upk(l0p[q], l0[2 * q], l0[2 * q + 1]);
            upk(l1p[q], l1[2 * q], l1[2 * q + 1]);
        }
        float mu0 = 0.0f, mu1 = 0.0f;
        #pragma unroll
        for (int i = 0; i < 8; i++) { mu0 += l0[i]; mu1 += l1[i]; }
        mu0 *= 0.125f; mu1 *= 0.125f;

        float v0 = 0.0f, v1 = 0.0f;
        #pragma unroll
        for (int i = 0; i < 8; i++) {
            float c0 = l0[i] - mu0, c1 = l1[i] - mu1;
            v0 += c0 * c0; v1 += c1 * c1;
        }
        float sc0 = 3.0f / (sqrtf(v0 * (1.0f / 7.0f)) + 1e-8f);
        float sc1 = 3.0f / (sqrtf(v1 * (1.0f / 7.0f)) + 1e-8f);

        float nz[16];
        {
            const float4* np = (const float4*)(noise + (size_t)b * 16);
            float4 q0 = np[0], q1 = np[1], q2 = np[2], q3 = np[3];
            nz[0]=q0.x; nz[1]=q0.y; nz[2]=q0.z; nz[3]=q0.w;
            nz[4]=q1.x; nz[5]=q1.y; nz[6]=q1.z; nz[7]=q1.w;
            nz[8]=q2.x; nz[9]=q2.y; nz[10]=q2.z; nz[11]=q2.w;
            nz[12]=q3.x; nz[13]=q3.y; nz[14]=q3.z; nz[15]=q3.w;
        }
        #pragma unroll
        for (int i = 0; i < 8; i++) {
            px[i] = ((l0[i] - mu0) * sc0) + nz[2 * i]     * 0.05f;
            py[i] = ((l1[i] - mu1) * sc1) + nz[2 * i + 1] * 0.05f;
        }
        float4* lp = (float4*)(out_lat + (size_t)b * 16);
        #pragma unroll
        for (int q = 0; q < 4; q++) {
            float4 o;
            o.x = px[2 * q];     o.y = py[2 * q];
            o.z = px[2 * q + 1]; o.w = py[2 * q + 1];
            lp[q] = o;
        }
    }

    // ---------------- P4: Gabriel graph (expression-identical) ----------------
    unsigned am = 0;
    int deg[8];
    #pragma unroll
    for (int i = 0; i < 8; i++) deg[i] = 1;

    #pragma unroll
    for (int i = 0; i < 8; i++) {
        #pragma unroll
        for (int j = i + 1; j < 8; j++) {
            float mx = (px[i] + px[j]) * 0.5f;
            float my = (py[i] + py[j]) * 0.5f;
            float dx = px[i] - mx, dy = py[i] - my;
            float r2 = dx * dx + dy * dy;
            float mind2 = 3.402823e38f;
            #pragma unroll
            for (int k = 0; k < 8; k++) {
                if (k != i && k != j) {
                    float ax = px[k] - mx, ay = py[k] - my;
                    mind2 = fminf(mind2, ax * ax + ay * ay);
                }
            }
            if (mind2 >= r2) {
                am |= (1u << PIDX(i, j));
                deg[i]++; deg[j]++;
            }
        }
    }

    float dinv[8];
    #pragma unroll
    for (int i = 0; i < 8; i++) dinv[i] = rsqrtf((float)deg[i]);

    // A output (raw 0/1 adjacency, zero diagonal)
    {
        float4* ap = (float4*)(out_A + (size_t)b * 64);
        #pragma unroll
        for (int i = 0; i < 8; i++) {
            float row[8];
            #pragma unroll
            for (int j = 0; j < 8; j++) {
                if (i == j) row[j] = 0.0f;
                else {
                    int p = (i < j) ? PIDX(i, j) : PIDX(j, i);
                    row[j] = ((am >> p) & 1u) ? 1.0f : 0.0f;
                }
            }
            ap[2 * i]     = make_float4(row[0], row[1], row[2], row[3]);
            ap[2 * i + 1] = make_float4(row[4], row[5], row[6], row[7]);
        }
    }

    // ---------------- P5: qx/qy/s via wx = dinv*px (predicated adds) --------
    u64 qx2[4], qy2[4], s2[4];
    {
        float wx[8], wy[8];
        #pragma unroll
        for (int j = 0; j < 8; j++) {
            wx[j] = dinv[j] * px[j];
            wy[j] = dinv[j] * py[j];
        }

        float tqx = 0.0f, tqy = 0.0f, ts = 0.0f;
        #pragma unroll
        for (int n = 0; n < 8; n++) {
            float tx = wx[n], ty = wy[n], td = dinv[n];
            #pragma unroll
            for (int j = 0; j < 8; j++) {
                if (j == n) continue;
                int p = (n < j) ? PIDX(n, j) : PIDX(j, n);
                bool adj = (am >> p) & 1u;
                if (adj) { tx += wx[j]; ty += wy[j]; td += dinv[j]; }
            }
            float qxn = dinv[n] * tx;
            float qyn = dinv[n] * ty;
            float sn  = dinv[n] * td * 0.125f;
            if (n & 1) {
                qx2[n >> 1] = pk(tqx, qxn);
                qy2[n >> 1] = pk(tqy, qyn);
                s2[n >> 1]  = pk(ts, sn);
            } else {
                tqx = qxn; tqy = qyn; ts = sn;
            }
        }
    }

    // ---------------- P6: GCN channel values u_c ----------------
    u64 u2[16];
    {
        float tu = 0.0f;
        #pragma unroll 2
        for (int c = 0; c < 32; c++) {
            float4 g   = sWg1q[c];
            float2 bgp = sWg1b[c];
            u64 g0d = pk(g.x, g.y), g1d = pk(g.z, g.w), bgd = pk(bgp.x, bgp.y);
            u64 acc2 = z2;
            #pragma unroll
            for (int q = 0; q < 4; q++) {
                u64 a = fma2(qx2[q], g0d, fma2(qy2[q], g1d, bgd));
                acc2 = fma2(s2[q], relu2(a), acc2);
            }
            float ua, ub; upk(acc2, ua, ub);
            float uc = ua + ub;
            if (c & 1) u2[c >> 1] = pk(tu, uc);
            else       tu = uc;
        }
    }

    // ---------------- P7: fused decoder -> recon (streamed M rows) ----------
    float recon = sbd2v;

    #pragma unroll 2
    for (int e = 0; e < 64; e++) {
        const float4* wr = &sMT4[e * 8];
        float2 cw = scw[e];
        u64 accA = z2, accB = z2;
        #pragma unroll
        for (int q = 0; q < 8; q++) {
            float4 f = wr[q];
            accA = fma2(u2[2 * q],     pk(f.x, f.y), accA);
            accB = fma2(u2[2 * q + 1], pk(f.z, f.w), accB);
        }
        u64 acc = add2(accA, accB);
        float sa, sb; upk(acc, sa, sb);
        float pre = (sa + sb) + cw.x;
        recon = fmaf(fmaxf(pre, 0.0f), cw.y, recon);
    }

    {
        float4 r4 = {recon, recon, recon, recon};
        float4* rp = (float4*)(out_recon + (size_t)b * 8);
        rp[0] = r4;
        rp[1] = r4;
    }
}

extern "C" void kernel_launch(void* const* d_in, const int* in_sizes, int n_in,
                              void* d_out, int out_size)
{
    const float* x     = (const float*)d_in[0];
    const float* noise = (const float*)d_in[1];
    const float* We1   = (const float*)d_in[2];
    const float* be1   = (const float*)d_in[3];
    const float* We2   = (const float*)d_in[4];
    const float* be2   = (const float*)d_in[5];
    const float* Wg1   = (const float*)d_in[6];
    const float* bg1   = (const float*)d_in[7];
    const float* Wg2   = (const float*)d_in[8];
    const float* bg2   = (const float*)d_in[9];
    const float* Wd1   = (const float*)d_in[10];
    const float* bd1   = (const float*)d_in[11];
    const float* Wd2   = (const float*)d_in[12];
    const float* bd2   = (const float*)d_in[13];

    const int nb = in_sizes[0] / NN;
    float* out = (float*)d_out;

    dim3 grid((nb + BLOCK - 1) / BLOCK);
    gae_kernel<<<grid, BLOCK>>>(x, noise, We1, be1, We2, be2, Wg1, bg1,
                                Wg2, bg2, Wd1, bd1, Wd2, bd2, out, nb);
}

// round 11
// speedup vs baseline: 1.0815x; 1.0006x over previous
#include <cuda_runtime.h>
#include <cstdint>

// R11: IB=1, BLOCK=128, 7 CTA/SM. LDS-traffic reduction:
//  - P7 decoder pair-split: lanes l and l^16 share M reads across 2 batches
//  - encoder c_i computed on the fly (bit-identical fma), sencC deleted
//  - Wg1 packed into one float4
// Lat/Gabriel/A arithmetic expression-identical to round 10.
// Output layout: [recon (nb*8)] [lat (nb*16)] [A (nb*64)]

constexpr int NN = 8;
constexpr int BLOCK = 128;

using u64 = unsigned long long;

__device__ __forceinline__ u64 pk(float lo, float hi) {
    u64 r; asm("mov.b64 %0, {%1,%2};" : "=l"(r) : "f"(lo), "f"(hi)); return r;
}
__device__ __forceinline__ void upk(u64 v, float& lo, float& hi) {
    asm("mov.b64 {%0,%1}, %2;" : "=f"(lo), "=f"(hi) : "l"(v));
}
__device__ __forceinline__ u64 fma2(u64 a, u64 b, u64 c) {
    u64 d; asm("fma.rn.f32x2 %0, %1, %2, %3;" : "=l"(d) : "l"(a), "l"(b), "l"(c)); return d;
}
__device__ __forceinline__ u64 add2(u64 a, u64 b) {
    u64 d; asm("add.rn.f32x2 %0, %1, %2;" : "=l"(d) : "l"(a), "l"(b)); return d;
}
__device__ __forceinline__ u64 dup2(float v) { return pk(v, v); }
__device__ __forceinline__ u64 relu2(u64 v) {
    float a, b; upk(v, a, b);
    return pk(fmaxf(a, 0.0f), fmaxf(b, 0.0f));
}
__device__ __forceinline__ u64 shflx_u64(u64 v, int m) {
    float lo, hi; upk(v, lo, hi);
    lo = __shfl_xor_sync(0xffffffffu, lo, m);
    hi = __shfl_xor_sync(0xffffffffu, hi, m);
    return pk(lo, hi);
}

__device__ __forceinline__ constexpr int PIDX(int i, int j) { // i<j, 0..27
    return i * 7 - (i * (i - 1)) / 2 + (j - i - 1);
}

__global__ void __launch_bounds__(BLOCK, 7)
gae_kernel(const float* __restrict__ x, const float* __restrict__ noise,
           const float* __restrict__ We1, const float* __restrict__ be1,
           const float* __restrict__ We2, const float* __restrict__ be2,
           const float* __restrict__ Wg1, const float* __restrict__ bg1,
           const float* __restrict__ Wg2, const float* __restrict__ bg2,
           const float* __restrict__ Wd1, const float* __restrict__ bd1,
           const float* __restrict__ Wd2, const float* __restrict__ bd2,
           float* __restrict__ out, int nb)
{
    __shared__ float4 sencP[64];        // (w1, w2, be, e0)
    __shared__ float2 sencE1[64];       // (e1, e1)
    __shared__ float4 sWg1p[32];        // (g0, g1, bg, 0)
    __shared__ float4 sMT4[64 * 8];     // fused decoder M[e][c], c contiguous
    __shared__ float2 scw[64];          // (bg2@Wd1 + bd1, Wd2[e][1])
    __shared__ float  sbd2v;
    __shared__ float  sWg2T[32 * 33];   // Wg2 transposed, padded (staging)
    __shared__ float4 sWd1s4[32 * 16];  // Wd1 staged: [d][pp]

    const int t = threadIdx.x;
    const u64 z2 = pk(0.0f, 0.0f);

    // ---- stage raw weights ----
    if (t < 64) {
        float w1 = We1[64 + t];
        float w2 = We1[128 + t];
        float be = be1[t];
        float e0 = We2[2 * t], e1 = We2[2 * t + 1];
        sencP[t]  = make_float4(w1, w2, be, e0);
        sencE1[t] = make_float2(e1, e1);
    }
    if (t < 32) {
        sWg1p[t] = make_float4(Wg1[t], Wg1[32 + t], bg1[t], 0.0f);
    }
    for (int idx = t; idx < 1024; idx += BLOCK) {
        int c = idx >> 5, d = idx & 31;
        sWg2T[d * 33 + c] = Wg2[idx];
    }
    for (int idx = t; idx < 512; idx += BLOCK) {
        sWd1s4[idx] = *(const float4*)&Wd1[4 * idx];
    }
    if (t == 0) sbd2v = bd2[1];
    __syncthreads();

    // ---- fused decoder weights: M[e][c] = sum_d Wg2[c][d]*Wd1[d][e] ----
    {
        int c = t & 31, ep0 = t >> 5;
        u64 acc[8];
        #pragma unroll
        for (int k = 0; k < 8; k++) acc[k] = z2;
        #pragma unroll 2
        for (int d = 0; d < 32; d++) {
            u64 ad = dup2(sWg2T[d * 33 + c]);
            float4 f0 = sWd1s4[d * 16 + ep0 * 4 + 0];
            float4 f1 = sWd1s4[d * 16 + ep0 * 4 + 1];
            float4 f2 = sWd1s4[d * 16 + ep0 * 4 + 2];
            float4 f3 = sWd1s4[d * 16 + ep0 * 4 + 3];
            acc[0] = fma2(ad, pk(f0.x, f0.y), acc[0]);
            acc[1] = fma2(ad, pk(f0.z, f0.w), acc[1]);
            acc[2] = fma2(ad, pk(f1.x, f1.y), acc[2]);
            acc[3] = fma2(ad, pk(f1.z, f1.w), acc[3]);
            acc[4] = fma2(ad, pk(f2.x, f2.y), acc[4]);
            acc[5] = fma2(ad, pk(f2.z, f2.w), acc[5]);
            acc[6] = fma2(ad, pk(f3.x, f3.y), acc[6]);
            acc[7] = fma2(ad, pk(f3.z, f3.w), acc[7]);
        }
        #pragma unroll
        for (int k = 0; k < 8; k++) {
            int p = ep0 * 8 + k;
            float mlo, mhi; upk(acc[k], mlo, mhi);
            ((float*)sMT4)[(2 * p)     * 32 + c] = mlo;
            ((float*)sMT4)[(2 * p + 1) * 32 + c] = mhi;
        }
    }
    if (t < 64) {
        float ce = bd1[t];
        int pp = t >> 2, r = t & 3;
        #pragma unroll
        for (int d = 0; d < 32; d++) {
            float4 w = sWd1s4[d * 16 + pp];
            float vv = (r & 2) ? ((r & 1) ? w.w : w.z) : ((r & 1) ? w.y : w.x);
            ce = fmaf(bg2[d], vv, ce);
        }
        scw[t] = make_float2(ce, Wd2[t * 3 + 1]);
    }
    __syncthreads();

    const int b = blockIdx.x * BLOCK + t;
    if (b >= nb) return;   // never taken for nb=131072 (exact grid fit)

    float* out_recon = out;
    float* out_lat   = out + (size_t)nb * 8;
    float* out_A     = out + (size_t)nb * 24;

    // ---------------- P0: load x ----------------
    u64 x2[4];
    {
        const float4* xp = (const float4*)(x + (size_t)b * 8);
        float4 a = xp[0], c = xp[1];
        x2[0] = pk(a.x, a.y); x2[1] = pk(a.z, a.w);
        x2[2] = pk(c.x, c.y); x2[3] = pk(c.z, c.w);
    }

    // ---------------- P1: encoder (c_i computed on the fly, bit-exact) -----
    const u64 iv[4] = { pk(0.0f, 1.0f), pk(2.0f, 3.0f),
                        pk(4.0f, 5.0f), pk(6.0f, 7.0f) };
    u64 l0p[4], l1p[4];
    #pragma unroll
    for (int q = 0; q < 4; q++) { l0p[q] = z2; l1p[q] = z2; }

    #pragma unroll 2
    for (int k = 0; k < 64; k++) {
        float4 w  = sencP[k];
        float2 e1 = sencE1[k];
        u64 w1d = dup2(w.x), w2d = dup2(w.y), bed = dup2(w.z);
        u64 e0d = dup2(w.w), e1d = pk(e1.x, e1.y);
        #pragma unroll
        for (int q = 0; q < 4; q++) {
            u64 c2q = fma2(iv[q], w2d, bed);           // == fmaf(i, w2, be)
            u64 h = relu2(fma2(x2[q], w1d, c2q));
            l0p[q] = fma2(h, e0d, l0p[q]);
            l1p[q] = fma2(h, e1d, l1p[q]);
        }
    }

    // ---------------- P2/P3: stats, noise, px/py, lat store ----------------
    float px[8], py[8];
    {
        float l0[8], l1[8];
        #pragma unroll
        for (int q = 0; q < 4; q++) {
            upk(l0p[q], l0[2 * q], l0[2 * q + 1]);
            upk(l1p[q], l1[2 * q], l1[2 * q + 1]);
        }
        float mu0 = 0.0f, mu1 = 0.0f;
        #pragma unroll
        for (int i = 0; i < 8; i++) { mu0 += l0[i]; mu1 += l1[i]; }
        mu0 *= 0.125f; mu1 *= 0.125f;

        float v0 = 0.0f, v1 = 0.0f;
        #pragma unroll
        for (int i = 0; i < 8; i++) {
            float c0 = l0[i] - mu0, c1 = l1[i] - mu1;
            v0 += c0 * c0; v1 += c1 * c1;
        }
        float sc0 = 3.0f / (sqrtf(v0 * (1.0f / 7.0f)) + 1e-8f);
        float sc1 = 3.0f / (sqrtf(v1 * (1.0f / 7.0f)) + 1e-8f);

        float nz[16];
        {
            const float4* np = (const float4*)(noise + (size_t)b * 16);
            float4 q0 = np[0], q1 = np[1], q2 = np[2], q3 = np[3];
            nz[0]=q0.x; nz[1]=q0.y; nz[2]=q0.z; nz[3]=q0.w;
            nz[4]=q1.x; nz[5]=q1.y; nz[6]=q1.z; nz[7]=q1.w;
            nz[8]=q2.x; nz[9]=q2.y; nz[10]=q2.z; nz[11]=q2.w;
            nz[12]=q3.x; nz[13]=q3.y; nz[14]=q3.z; nz[15]=q3.w;
        }
        #pragma unroll
        for (int i = 0; i < 8; i++) {
            px[i] = ((l0[i] - mu0) * sc0) + nz[2 * i]     * 0.05f;
            py[i] = ((l1[i] - mu1) * sc1) + nz[2 * i + 1] * 0.05f;
        }
        float4* lp = (float4*)(out_lat + (size_t)b * 16);
        #pragma unroll
        for (int q = 0; q < 4; q++) {
            float4 o;
            o.x = px[2 * q];     o.y = py[2 * q];
            o.z = px[2 * q + 1]; o.w = py[2 * q + 1];
            lp[q] = o;
        }
    }

    // ---------------- P4: Gabriel graph (expression-identical) ----------------
    unsigned am = 0;
    int deg[8];
    #pragma unroll
    for (int i = 0; i < 8; i++) deg[i] = 1;

    #pragma unroll
    for (int i = 0; i < 8; i++) {
        #pragma unroll
        for (int j = i + 1; j < 8; j++) {
            float mx = (px[i] + px[j]) * 0.5f;
            float my = (py[i] + py[j]) * 0.5f;
            float dx = px[i] - mx, dy = py[i] - my;
            float r2 = dx * dx + dy * dy;
            float mind2 = 3.402823e38f;
            #pragma unroll
            for (int k = 0; k < 8; k++) {
                if (k != i && k != j) {
                    float ax = px[k] - mx, ay = py[k] - my;
                    mind2 = fminf(mind2, ax * ax + ay * ay);
                }
            }
            if (mind2 >= r2) {
                am |= (1u << PIDX(i, j));
                deg[i]++; deg[j]++;
            }
        }
    }

    float dinv[8];
    #pragma unroll
    for (int i = 0; i < 8; i++) dinv[i] = rsqrtf((float)deg[i]);

    // A output (raw 0/1 adjacency, zero diagonal)
    {
        float4* ap = (float4*)(out_A + (size_t)b * 64);
        #pragma unroll
        for (int i = 0; i < 8; i++) {
            float row[8];
            #pragma unroll
            for (int j = 0; j < 8; j++) {
                if (i == j) row[j] = 0.0f;
                else {
                    int p = (i < j) ? PIDX(i, j) : PIDX(j, i);
                    row[j] = ((am >> p) & 1u) ? 1.0f : 0.0f;
                }
            }
            ap[2 * i]     = make_float4(row[0], row[1], row[2], row[3]);
            ap[2 * i + 1] = make_float4(row[4], row[5], row[6], row[7]);
        }
    }

    // ---------------- P5: qx/qy/s via wx = dinv*px (predicated adds) --------
    u64 qx2[4], qy2[4], s2[4];
    {
        float wx[8], wy[8];
        #pragma unroll
        for (int j = 0; j < 8; j++) {
            wx[j] = dinv[j] * px[j];
            wy[j] = dinv[j] * py[j];
        }

        float tqx = 0.0f, tqy = 0.0f, ts = 0.0f;
        #pragma unroll
        for (int n = 0; n < 8; n++) {
            float tx = wx[n], ty = wy[n], td = dinv[n];
            #pragma unroll
            for (int j = 0; j < 8; j++) {
                if (j == n) continue;
                int p = (n < j) ? PIDX(n, j) : PIDX(j, n);
                bool adj = (am >> p) & 1u;
                if (adj) { tx += wx[j]; ty += wy[j]; td += dinv[j]; }
            }
            float qxn = dinv[n] * tx;
            float qyn = dinv[n] * ty;
            float sn  = dinv[n] * td * 0.125f;
            if (n & 1) {
                qx2[n >> 1] = pk(tqx, qxn);
                qy2[n >> 1] = pk(tqy, qyn);
                s2[n >> 1]  = pk(ts, sn);
            } else {
                tqx = qxn; tqy = qyn; ts = sn;
            }
        }
    }

    // ---------------- P6: GCN channel values u_c ----------------
    u64 u2[16];
    {
        float tu = 0.0f;
        #pragma unroll 2
        for (int c = 0; c < 32; c++) {
            float4 g = sWg1p[c];
            u64 g0d = dup2(g.x), g1d = dup2(g.y), bgd = dup2(g.z);
            u64 acc2 = z2;
            #pragma unroll
            for (int q = 0; q < 4; q++) {
                u64 a = fma2(qx2[q], g0d, fma2(qy2[q], g1d, bgd));
                acc2 = fma2(s2[q], relu2(a), acc2);
            }
            float ua, ub; upk(acc2, ua, ub);
            float uc = ua + ub;
            if (c & 1) u2[c >> 1] = pk(tu, uc);
            else       tu = uc;
        }
    }

    // ---------------- P7: pair-split decoder (lanes l, l^16 share M reads) --
    // Lane with (lane&16)==0 handles q-half [0,4) (M cols 0..15);
    // the other handles q-half [4,8) (cols 16..31) — for BOTH batches.
    float recon = sbd2v;
    {
        const int lane = t & 31;
        const bool lowq = (lane & 16) == 0;

        u64 uo[8], up_[8];
        #pragma unroll
        for (int k = 0; k < 8; k++) {
            uo[k]     = lowq ? u2[k]     : u2[k + 8];   // own batch, my q-half
            u64 snd   = lowq ? u2[k + 8] : u2[k];       // partner's needed half
            up_[k]    = shflx_u64(snd, 16);             // partner batch, my q-half
        }

        const int colbase = lowq ? 0 : 4;
        #pragma unroll 2
        for (int e = 0; e < 64; e++) {
            const float4* wr = &sMT4[e * 8 + colbase];
            float4 f0 = wr[0], f1 = wr[1], f2 = wr[2], f3 = wr[3];
            u64 m0 = pk(f0.x, f0.y), m1 = pk(f0.z, f0.w);
            u64 m2 = pk(f1.x, f1.y), m3 = pk(f1.z, f1.w);
            u64 m4 = pk(f2.x, f2.y), m5 = pk(f2.z, f2.w);
            u64 m6 = pk(f3.x, f3.y), m7 = pk(f3.z, f3.w);

            // own-batch partial over my q-half
            u64 aA = fma2(uo[0], m0, z2); u64 aB = fma2(uo[1], m1, z2);
            aA = fma2(uo[2], m2, aA);     aB = fma2(uo[3], m3, aB);
            aA = fma2(uo[4], m4, aA);     aB = fma2(uo[5], m5, aB);
            aA = fma2(uo[6], m6, aA);     aB = fma2(uo[7], m7, aB);
            u64 ao = add2(aA, aB);
            float oa, ob; upk(ao, oa, ob);
            float p_own = oa + ob;

            // partner-batch partial over my q-half
            u64 bA = fma2(up_[0], m0, z2); u64 bB = fma2(up_[1], m1, z2);
            bA = fma2(up_[2], m2, bA);     bB = fma2(up_[3], m3, bB);
            bA = fma2(up_[4], m4, bA);     bB = fma2(up_[5], m5, bB);
            bA = fma2(up_[6], m6, bA);     bB = fma2(up_[7], m7, bB);
            u64 bo = add2(bA, bB);
            float pa, pb; upk(bo, pa, pb);
            float p_oth = pa + pb;

            // exchange: I receive my own batch's other-half partial
            float p_rcv = __shfl_xor_sync(0xffffffffu, p_oth, 16);

            float2 cw = scw[e];
            float pre = (p_own + p_rcv) + cw.x;
            recon = fmaf(fmaxf(pre, 0.0f), cw.y, recon);
        }
    }

    {
        float4 r4 = {recon, recon, recon, recon};
        float4* rp = (float4*)(out_recon + (size_t)b * 8);
        rp[0] = r4;
        rp[1] = r4;
    }
}

extern "C" void kernel_launch(void* const* d_in, const int* in_sizes, int n_in,
                              void* d_out, int out_size)
{
    const float* x     = (const float*)d_in[0];
    const float* noise = (const float*)d_in[1];
    const float* We1   = (const float*)d_in[2];
    const float* be1   = (const float*)d_in[3];
    const float* We2   = (const float*)d_in[4];
    const float* be2   = (const float*)d_in[5];
    const float* Wg1   = (const float*)d_in[6];
    const float* bg1   = (const float*)d_in[7];
    const float* Wg2   = (const float*)d_in[8];
    const float* bg2   = (const float*)d_in[9];
    const float* Wd1   = (const float*)d_in[10];
    const float* bd1   = (const float*)d_in[11];
    const float* Wd2   = (const float*)d_in[12];
    const float* bd2   = (const float*)d_in[13];

    const int nb = in_sizes[0] / NN;
    float* out = (float*)d_out;

    dim3 grid((nb + BLOCK - 1) / BLOCK);
    gae_kernel<<<grid, BLOCK>>>(x, noise, We1, be1, We2, be2, Wg1, bg1,
                                Wg2, bg2, Wd1, bd1, Wd2, bd2, out, nb);
}

// round 12
// speedup vs baseline: 1.1578x; 1.0705x over previous
#include <cuda_runtime.h>
#include <cstdint>

// R12 = R11 + coalesced A stores (bitmask shuffle decode) + P7 warp rotation.
// Lat/A outputs bit-identical to R11; recon differs only in last-bit rounding.
// Output layout: [recon (nb*8)] [lat (nb*16)] [A (nb*64)]

constexpr int NN = 8;
constexpr int BLOCK = 128;

using u64 = unsigned long long;

__device__ __forceinline__ u64 pk(float lo, float hi) {
    u64 r; asm("mov.b64 %0, {%1,%2};" : "=l"(r) : "f"(lo), "f"(hi)); return r;
}
__device__ __forceinline__ void upk(u64 v, float& lo, float& hi) {
    asm("mov.b64 {%0,%1}, %2;" : "=f"(lo), "=f"(hi) : "l"(v));
}
__device__ __forceinline__ u64 fma2(u64 a, u64 b, u64 c) {
    u64 d; asm("fma.rn.f32x2 %0, %1, %2, %3;" : "=l"(d) : "l"(a), "l"(b), "l"(c)); return d;
}
__device__ __forceinline__ u64 add2(u64 a, u64 b) {
    u64 d; asm("add.rn.f32x2 %0, %1, %2;" : "=l"(d) : "l"(a), "l"(b)); return d;
}
__device__ __forceinline__ u64 dup2(float v) { return pk(v, v); }
__device__ __forceinline__ u64 relu2(u64 v) {
    float a, b; upk(v, a, b);
    return pk(fmaxf(a, 0.0f), fmaxf(b, 0.0f));
}
__device__ __forceinline__ u64 shflx_u64(u64 v, int m) {
    float lo, hi; upk(v, lo, hi);
    lo = __shfl_xor_sync(0xffffffffu, lo, m);
    hi = __shfl_xor_sync(0xffffffffu, hi, m);
    return pk(lo, hi);
}

__device__ __forceinline__ constexpr int PIDX(int i, int j) { // i<j, 0..27
    return i * 7 - (i * (i - 1)) / 2 + (j - i - 1);
}

__global__ void __launch_bounds__(BLOCK, 7)
gae_kernel(const float* __restrict__ x, const float* __restrict__ noise,
           const float* __restrict__ We1, const float* __restrict__ be1,
           const float* __restrict__ We2, const float* __restrict__ be2,
           const float* __restrict__ Wg1, const float* __restrict__ bg1,
           const float* __restrict__ Wg2, const float* __restrict__ bg2,
           const float* __restrict__ Wd1, const float* __restrict__ bd1,
           const float* __restrict__ Wd2, const float* __restrict__ bd2,
           float* __restrict__ out, int nb)
{
    __shared__ float4 sencP[64];        // (w1, w2, be, e0)
    __shared__ float2 sencE1[64];       // (e1, e1)
    __shared__ float4 sWg1p[32];        // (g0, g1, bg, 0)
    __shared__ float4 sMT4[64 * 8];     // fused decoder M[e][c], c contiguous
    __shared__ float2 scw[64];          // (bg2@Wd1 + bd1, Wd2[e][1])
    __shared__ float  sbd2v;
    __shared__ float  sWg2T[32 * 33];   // Wg2 transposed, padded (staging)
    __shared__ float4 sWd1s4[32 * 16];  // Wd1 staged: [d][pp]

    const int t = threadIdx.x;
    const u64 z2 = pk(0.0f, 0.0f);

    // ---- stage raw weights ----
    if (t < 64) {
        float w1 = We1[64 + t];
        float w2 = We1[128 + t];
        float be = be1[t];
        float e0 = We2[2 * t], e1 = We2[2 * t + 1];
        sencP[t]  = make_float4(w1, w2, be, e0);
        sencE1[t] = make_float2(e1, e1);
    }
    if (t < 32) {
        sWg1p[t] = make_float4(Wg1[t], Wg1[32 + t], bg1[t], 0.0f);
    }
    for (int idx = t; idx < 1024; idx += BLOCK) {
        int c = idx >> 5, d = idx & 31;
        sWg2T[d * 33 + c] = Wg2[idx];
    }
    for (int idx = t; idx < 512; idx += BLOCK) {
        sWd1s4[idx] = *(const float4*)&Wd1[4 * idx];
    }
    if (t == 0) sbd2v = bd2[1];
    __syncthreads();

    // ---- fused decoder weights: M[e][c] = sum_d Wg2[c][d]*Wd1[d][e] ----
    {
        int c = t & 31, ep0 = t >> 5;
        u64 acc[8];
        #pragma unroll
        for (int k = 0; k < 8; k++) acc[k] = z2;
        #pragma unroll 2
        for (int d = 0; d < 32; d++) {
            u64 ad = dup2(sWg2T[d * 33 + c]);
            float4 f0 = sWd1s4[d * 16 + ep0 * 4 + 0];
            float4 f1 = sWd1s4[d * 16 + ep0 * 4 + 1];
            float4 f2 = sWd1s4[d * 16 + ep0 * 4 + 2];
            float4 f3 = sWd1s4[d * 16 + ep0 * 4 + 3];
            acc[0] = fma2(ad, pk(f0.x, f0.y), acc[0]);
            acc[1] = fma2(ad, pk(f0.z, f0.w), acc[1]);
            acc[2] = fma2(ad, pk(f1.x, f1.y), acc[2]);
            acc[3] = fma2(ad, pk(f1.z, f1.w), acc[3]);
            acc[4] = fma2(ad, pk(f2.x, f2.y), acc[4]);
            acc[5] = fma2(ad, pk(f2.z, f2.w), acc[5]);
            acc[6] = fma2(ad, pk(f3.x, f3.y), acc[6]);
            acc[7] = fma2(ad, pk(f3.z, f3.w), acc[7]);
        }
        #pragma unroll
        for (int k = 0; k < 8; k++) {
            int p = ep0 * 8 + k;
            float mlo, mhi; upk(acc[k], mlo, mhi);
            ((float*)sMT4)[(2 * p)     * 32 + c] = mlo;
            ((float*)sMT4)[(2 * p + 1) * 32 + c] = mhi;
        }
    }
    if (t < 64) {
        float ce = bd1[t];
        int pp = t >> 2, r = t & 3;
        #pragma unroll
        for (int d = 0; d < 32; d++) {
            float4 w = sWd1s4[d * 16 + pp];
            float vv = (r & 2) ? ((r & 1) ? w.w : w.z) : ((r & 1) ? w.y : w.x);
            ce = fmaf(bg2[d], vv, ce);
        }
        scw[t] = make_float2(ce, Wd2[t * 3 + 1]);
    }
    __syncthreads();

    const int b = blockIdx.x * BLOCK + t;
    if (b >= nb) return;   // never taken for nb=131072 (exact grid fit)

    float* out_recon = out;
    float* out_lat   = out + (size_t)nb * 8;
    float* out_A     = out + (size_t)nb * 24;

    // ---------------- P0: load x ----------------
    u64 x2[4];
    {
        const float4* xp = (const float4*)(x + (size_t)b * 8);
        float4 a = xp[0], c = xp[1];
        x2[0] = pk(a.x, a.y); x2[1] = pk(a.z, a.w);
        x2[2] = pk(c.x, c.y); x2[3] = pk(c.z, c.w);
    }

    // ---------------- P1: encoder (c_i computed on the fly, bit-exact) -----
    const u64 iv[4] = { pk(0.0f, 1.0f), pk(2.0f, 3.0f),
                        pk(4.0f, 5.0f), pk(6.0f, 7.0f) };
    u64 l0p[4], l1p[4];
    #pragma unroll
    for (int q = 0; q < 4; q++) { l0p[q] = z2; l1p[q] = z2; }

    #pragma unroll 2
    for (int k = 0; k < 64; k++) {
        float4 w  = sencP[k];
        float2 e1 = sencE1[k];
        u64 w1d = dup2(w.x), w2d = dup2(w.y), bed = dup2(w.z);
        u64 e0d = dup2(w.w), e1d = pk(e1.x, e1.y);
        #pragma unroll
        for (int q = 0; q < 4; q++) {
            u64 c2q = fma2(iv[q], w2d, bed);           // == fmaf(i, w2, be)
            u64 h = relu2(fma2(x2[q], w1d, c2q));
            l0p[q] = fma2(h, e0d, l0p[q]);
            l1p[q] = fma2(h, e1d, l1p[q]);
        }
    }

    // ---------------- P2/P3: stats, noise, px/py, lat store ----------------
    float px[8], py[8];
    {
        float l0[8], l1[8];
        #pragma unroll
        for (int q = 0; q < 4; q++) {
            upk(l0p[q], l0[2 * q], l0[2 * q + 1]);
            upk(l1p[q], l1[2 * q], l1[2 * q + 1]);
        }
        float mu0 = 0.0f, mu1 = 0.0f;
        #pragma unroll
        for (int i = 0; i < 8; i++) { mu0 += l0[i]; mu1 += l1[i]; }
        mu0 *= 0.125f; mu1 *= 0.125f;

        float v0 = 0.0f, v1 = 0.0f;
        #pragma unroll
        for (int i = 0; i < 8; i++) {
            float c0 = l0[i] - mu0, c1 = l1[i] - mu1;
            v0 += c0 * c0; v1 += c1 * c1;
        }
        float sc0 = 3.0f / (sqrtf(v0 * (1.0f / 7.0f)) + 1e-8f);
        float sc1 = 3.0f / (sqrtf(v1 * (1.0f / 7.0f)) + 1e-8f);

        float nz[16];
        {
            const float4* np = (const float4*)(noise + (size_t)b * 16);
            float4 q0 = np[0], q1 = np[1], q2 = np[2], q3 = np[3];
            nz[0]=q0.x; nz[1]=q0.y; nz[2]=q0.z; nz[3]=q0.w;
            nz[4]=q1.x; nz[5]=q1.y; nz[6]=q1.z; nz[7]=q1.w;
            nz[8]=q2.x; nz[9]=q2.y; nz[10]=q2.z; nz[11]=q2.w;
            nz[12]=q3.x; nz[13]=q3.y; nz[14]=q3.z; nz[15]=q3.w;
        }
        #pragma unroll
        for (int i = 0; i < 8; i++) {
            px[i] = ((l0[i] - mu0) * sc0) + nz[2 * i]     * 0.05f;
            py[i] = ((l1[i] - mu1) * sc1) + nz[2 * i + 1] * 0.05f;
        }
        float4* lp = (float4*)(out_lat + (size_t)b * 16);
        #pragma unroll
        for (int q = 0; q < 4; q++) {
            float4 o;
            o.x = px[2 * q];     o.y = py[2 * q];
            o.z = px[2 * q + 1]; o.w = py[2 * q + 1];
            lp[q] = o;
        }
    }

    // ---------------- P4: Gabriel graph (expression-identical) ----------------
    unsigned am = 0;
    int deg[8];
    #pragma unroll
    for (int i = 0; i < 8; i++) deg[i] = 1;

    #pragma unroll
    for (int i = 0; i < 8; i++) {
        #pragma unroll
        for (int j = i + 1; j < 8; j++) {
            float mx = (px[i] + px[j]) * 0.5f;
            float my = (py[i] + py[j]) * 0.5f;
            float dx = px[i] - mx, dy = py[i] - my;
            float r2 = dx * dx + dy * dy;
            float mind2 = 3.402823e38f;
            #pragma unroll
            for (int k = 0; k < 8; k++) {
                if (k != i && k != j) {
                    float ax = px[k] - mx, ay = py[k] - my;
                    mind2 = fminf(mind2, ax * ax + ay * ay);
                }
            }
            if (mind2 >= r2) {
                am |= (1u << PIDX(i, j));
                deg[i]++; deg[j]++;
            }
        }
    }

    float dinv[8];
    #pragma unroll
    for (int i = 0; i < 8; i++) dinv[i] = rsqrtf((float)deg[i]);

    // ---------------- A output: warp-coalesced via bitmask shuffle ----------
    // float4 #f of the warp's 512-float4 A region maps to:
    //   batch_local = f>>4, m = f&15, row = m>>1, cols = (m&1)*4 .. +3
    // Lane l, iter k: f = 32k + l -> batch_local = 2k + (l>>4), m = l&15.
    // Shift=31 encodes the diagonal (bit 31 of am is always 0 -> 0.0f).
    {
        const int lane = t & 31;
        const int m_  = lane & 15;
        const int ai_ = m_ >> 1;
        const int jb  = (m_ & 1) * 4;
        int sh[4];
        #pragma unroll
        for (int jj = 0; jj < 4; jj++) {
            int j = jb + jj;
            if (j == ai_) sh[jj] = 31;
            else {
                int lo = ai_ < j ? ai_ : j;
                int hi = ai_ < j ? j : ai_;
                sh[jj] = lo * 7 - (lo * (lo - 1)) / 2 + (hi - lo - 1);
            }
        }
        float4* warpA = (float4*)(out_A + (size_t)(blockIdx.x * BLOCK + (t & ~31)) * 64);
        #pragma unroll
        for (int k = 0; k < 16; k++) {
            unsigned a = __shfl_sync(0xffffffffu, am, 2 * k + (lane >> 4));
            float4 o;
            o.x = ((a >> sh[0]) & 1u) ? 1.0f : 0.0f;
            o.y = ((a >> sh[1]) & 1u) ? 1.0f : 0.0f;
            o.z = ((a >> sh[2]) & 1u) ? 1.0f : 0.0f;
            o.w = ((a >> sh[3]) & 1u) ? 1.0f : 0.0f;
            warpA[k * 32 + lane] = o;
        }
    }

    // ---------------- P5: qx/qy/s via wx = dinv*px (predicated adds) --------
    u64 qx2[4], qy2[4], s2[4];
    {
        float wx[8], wy[8];
        #pragma unroll
        for (int j = 0; j < 8; j++) {
            wx[j] = dinv[j] * px[j];
            wy[j] = dinv[j] * py[j];
        }

        float tqx = 0.0f, tqy = 0.0f, ts = 0.0f;
        #pragma unroll
        for (int n = 0; n < 8; n++) {
            float tx = wx[n], ty = wy[n], td = dinv[n];
            #pragma unroll
            for (int j = 0; j < 8; j++) {
                if (j == n) continue;
                int p = (n < j) ? PIDX(n, j) : PIDX(j, n);
                bool adj = (am >> p) & 1u;
                if (adj) { tx += wx[j]; ty += wy[j]; td += dinv[j]; }
            }
            float qxn = dinv[n] * tx;
            float qyn = dinv[n] * ty;
            float sn  = dinv[n] * td * 0.125f;
            if (n & 1) {
                qx2[n >> 1] = pk(tqx, qxn);
                qy2[n >> 1] = pk(tqy, qyn);
                s2[n >> 1]  = pk(ts, sn);
            } else {
                tqx = qxn; tqy = qyn; ts = sn;
            }
        }
    }

    // ---------------- P6: GCN channel values u_c ----------------
    u64 u2[16];
    {
        float tu = 0.0f;
        #pragma unroll 2
        for (int c = 0; c < 32; c++) {
            float4 g = sWg1p[c];
            u64 g0d = dup2(g.x), g1d = dup2(g.y), bgd = dup2(g.z);
            u64 acc2 = z2;
            #pragma unroll
            for (int q = 0; q < 4; q++) {
                u64 a = fma2(qx2[q], g0d, fma2(qy2[q], g1d, bgd));
                acc2 = fma2(s2[q], relu2(a), acc2);
            }
            float ua, ub; upk(acc2, ua, ub);
            float uc = ua + ub;
            if (c & 1) u2[c >> 1] = pk(tu, uc);
            else       tu = uc;
        }
    }

    // ---------------- P7: pair-split decoder, warp-rotated e order ----------
    float recon = sbd2v;
    {
        const int lane = t & 31;
        const bool lowq = (lane & 16) == 0;
        const int rot = (t >> 5) << 4;               // 0,16,32,48 per warp

        u64 uo[8], up_[8];
        #pragma unroll
        for (int k = 0; k < 8; k++) {
            uo[k]   = lowq ? u2[k]     : u2[k + 8];
            u64 snd = lowq ? u2[k + 8] : u2[k];
            up_[k]  = shflx_u64(snd, 16);
        }

        const int colbase = lowq ? 0 : 4;
        #pragma unroll 2
        for (int ee = 0; ee < 64; ee++) {
            int e = (ee + rot) & 63;
            const float4* wr = &sMT4[e * 8 + colbase];
            float4 f0 = wr[0], f1 = wr[1], f2 = wr[2], f3 = wr[3];
            u64 m0 = pk(f0.x, f0.y), m1 = pk(f0.z, f0.w);
            u64 m2 = pk(f1.x, f1.y), m3 = pk(f1.z, f1.w);
            u64 m4 = pk(f2.x, f2.y), m5 = pk(f2.z, f2.w);
            u64 m6 = pk(f3.x, f3.y), m7 = pk(f3.z, f3.w);

            u64 aA = fma2(uo[0], m0, z2); u64 aB = fma2(uo[1], m1, z2);
            aA = fma2(uo[2], m2, aA);     aB = fma2(uo[3], m3, aB);
            aA = fma2(uo[4], m4, aA);     aB = fma2(uo[5], m5, aB);
            aA = fma2(uo[6], m6, aA);     aB = fma2(uo[7], m7, aB);
            u64 ao = add2(aA, aB);
            float oa, ob; upk(ao, oa, ob);
            float p_own = oa + ob;

            u64 bA = fma2(up_[0], m0, z2); u64 bB = fma2(up_[1], m1, z2);
            bA = fma2(up_[2], m2, bA);     bB = fma2(up_[3], m3, bB);
            bA = fma2(up_[4], m4, bA);     bB = fma2(up_[5], m5, bB);
            bA = fma2(up_[6], m6, bA);     bB = fma2(up_[7], m7, bB);
            u64 bo = add2(bA, bB);
            float pa, pb; upk(bo, pa, pb);
            float p_oth = pa + pb;

            float p_rcv = __shfl_xor_sync(0xffffffffu, p_oth, 16);

            float2 cw = scw[e];
            float pre = (p_own + p_rcv) + cw.x;
            recon = fmaf(fmaxf(pre, 0.0f), cw.y, recon);
        }
    }

    {
        float4 r4 = {recon, recon, recon, recon};
        float4* rp = (float4*)(out_recon + (size_t)b * 8);
        rp[0] = r4;
        rp[1] = r4;
    }
}

extern "C" void kernel_launch(void* const* d_in, const int* in_sizes, int n_in,
                              void* d_out, int out_size)
{
    const float* x     = (const float*)d_in[0];
    const float* noise = (const float*)d_in[1];
    const float* We1   = (const float*)d_in[2];
    const float* be1   = (const float*)d_in[3];
    const float* We2   = (const float*)d_in[4];
    const float* be2   = (const float*)d_in[5];
    const float* Wg1   = (const float*)d_in[6];
    const float* bg1   = (const float*)d_in[7];
    const float* Wg2   = (const float*)d_in[8];
    const float* bg2   = (const float*)d_in[9];
    const float* Wd1   = (const float*)d_in[10];
    const float* bd1   = (const float*)d_in[11];
    const float* Wd2   = (const float*)d_in[12];
    const float* bd2   = (const float*)d_in[13];

    const int nb = in_sizes[0] / NN;
    float* out = (float*)d_out;

    dim3 grid((nb + BLOCK - 1) / BLOCK);
    gae_kernel<<<grid, BLOCK>>>(x, noise, We1, be1, We2, be2, Wg1, bg1,
                                Wg2, bg2, Wd1, bd1, Wd2, bd2, out, nb);
}

// round 13
// speedup vs baseline: 1.1592x; 1.0012x over previous
#include <cuda_runtime.h>
#include <cstdint>

// R13 = R12 (coalesced A stores, pair-split P7) with encoder/P6 weight staging
// reverted to pre-duplicated smem pairs + staged sencC (R10 style):
// moves ~650 fma/alu issue slots per thread onto the idle LSU pipe.
// Lat/Gabriel/A outputs bit-identical to R12.
// Output layout: [recon (nb*8)] [lat (nb*16)] [A (nb*64)]

constexpr int NN = 8;
constexpr int BLOCK = 128;

using u64 = unsigned long long;

__device__ __forceinline__ u64 pk(float lo, float hi) {
    u64 r; asm("mov.b64 %0, {%1,%2};" : "=l"(r) : "f"(lo), "f"(hi)); return r;
}
__device__ __forceinline__ void upk(u64 v, float& lo, float& hi) {
    asm("mov.b64 {%0,%1}, %2;" : "=f"(lo), "=f"(hi) : "l"(v));
}
__device__ __forceinline__ u64 fma2(u64 a, u64 b, u64 c) {
    u64 d; asm("fma.rn.f32x2 %0, %1, %2, %3;" : "=l"(d) : "l"(a), "l"(b), "l"(c)); return d;
}
__device__ __forceinline__ u64 add2(u64 a, u64 b) {
    u64 d; asm("add.rn.f32x2 %0, %1, %2;" : "=l"(d) : "l"(a), "l"(b)); return d;
}
__device__ __forceinline__ u64 dup2(float v) { return pk(v, v); }
__device__ __forceinline__ u64 relu2(u64 v) {
    float a, b; upk(v, a, b);
    return pk(fmaxf(a, 0.0f), fmaxf(b, 0.0f));
}
__device__ __forceinline__ u64 shflx_u64(u64 v, int m) {
    float lo, hi; upk(v, lo, hi);
    lo = __shfl_xor_sync(0xffffffffu, lo, m);
    hi = __shfl_xor_sync(0xffffffffu, hi, m);
    return pk(lo, hi);
}

__device__ __forceinline__ constexpr int PIDX(int i, int j) { // i<j, 0..27
    return i * 7 - (i * (i - 1)) / 2 + (j - i - 1);
}

__global__ void __launch_bounds__(BLOCK, 7)
gae_kernel(const float* __restrict__ x, const float* __restrict__ noise,
           const float* __restrict__ We1, const float* __restrict__ be1,
           const float* __restrict__ We2, const float* __restrict__ be2,
           const float* __restrict__ Wg1, const float* __restrict__ bg1,
           const float* __restrict__ Wg2, const float* __restrict__ bg2,
           const float* __restrict__ Wd1, const float* __restrict__ bd1,
           const float* __restrict__ Wd2, const float* __restrict__ bd2,
           float* __restrict__ out, int nb)
{
    __shared__ float4 sencWq[64];       // (w1,w1, e0,e0)
    __shared__ float2 sencE1[64];       // (e1,e1)
    __shared__ float4 sencC[128];       // [k][2]: c_i = fmaf(i, w2, be1)
    __shared__ float4 sWg1q[32];        // (g0,g0, g1,g1)
    __shared__ float2 sWg1b[32];        // (bg,bg)
    __shared__ float4 sMT4[64 * 8];     // fused decoder M[e][c], c contiguous
    __shared__ float2 scw[64];          // (bg2@Wd1 + bd1, Wd2[e][1])
    __shared__ float  sbd2v;
    __shared__ float  sWg2T[32 * 33];   // Wg2 transposed, padded (staging)
    __shared__ float4 sWd1s4[32 * 16];  // Wd1 staged: [d][pp]

    const int t = threadIdx.x;
    const u64 z2 = pk(0.0f, 0.0f);

    // ---- stage raw weights ----
    if (t < 64) {
        float w1 = We1[64 + t];
        float w2 = We1[128 + t];
        float be = be1[t];
        float e0 = We2[2 * t], e1 = We2[2 * t + 1];
        sencWq[t] = make_float4(w1, w1, e0, e0);
        sencE1[t] = make_float2(e1, e1);
        float c[8];
        #pragma unroll
        for (int i = 0; i < 8; i++) c[i] = fmaf((float)i, w2, be);
        sencC[2 * t]     = make_float4(c[0], c[1], c[2], c[3]);
        sencC[2 * t + 1] = make_float4(c[4], c[5], c[6], c[7]);
    }
    if (t < 32) {
        float g0 = Wg1[t], g1 = Wg1[32 + t], bg = bg1[t];
        sWg1q[t] = make_float4(g0, g0, g1, g1);
        sWg1b[t] = make_float2(bg, bg);
    }
    for (int idx = t; idx < 1024; idx += BLOCK) {
        int c = idx >> 5, d = idx & 31;
        sWg2T[d * 33 + c] = Wg2[idx];
    }
    for (int idx = t; idx < 512; idx += BLOCK) {
        sWd1s4[idx] = *(const float4*)&Wd1[4 * idx];
    }
    if (t == 0) sbd2v = bd2[1];
    __syncthreads();

    // ---- fused decoder weights: M[e][c] = sum_d Wg2[c][d]*Wd1[d][e] ----
    {
        int c = t & 31, ep0 = t >> 5;
        u64 acc[8];
        #pragma unroll
        for (int k = 0; k < 8; k++) acc[k] = z2;
        #pragma unroll 2
        for (int d = 0; d < 32; d++) {
            u64 ad = dup2(sWg2T[d * 33 + c]);
            float4 f0 = sWd1s4[d * 16 + ep0 * 4 + 0];
            float4 f1 = sWd1s4[d * 16 + ep0 * 4 + 1];
            float4 f2 = sWd1s4[d * 16 + ep0 * 4 + 2];
            float4 f3 = sWd1s4[d * 16 + ep0 * 4 + 3];
            acc[0] = fma2(ad, pk(f0.x, f0.y), acc[0]);
            acc[1] = fma2(ad, pk(f0.z, f0.w), acc[1]);
            acc[2] = fma2(ad, pk(f1.x, f1.y), acc[2]);
            acc[3] = fma2(ad, pk(f1.z, f1.w), acc[3]);
            acc[4] = fma2(ad, pk(f2.x, f2.y), acc[4]);
            acc[5] = fma2(ad, pk(f2.z, f2.w), acc[5]);
            acc[6] = fma2(ad, pk(f3.x, f3.y), acc[6]);
            acc[7] = fma2(ad, pk(f3.z, f3.w), acc[7]);
        }
        #pragma unroll
        for (int k = 0; k < 8; k++) {
            int p = ep0 * 8 + k;
            float mlo, mhi; upk(acc[k], mlo, mhi);
            ((float*)sMT4)[(2 * p)     * 32 + c] = mlo;
            ((float*)sMT4)[(2 * p + 1) * 32 + c] = mhi;
        }
    }
    if (t < 64) {
        float ce = bd1[t];
        int pp = t >> 2, r = t & 3;
        #pragma unroll
        for (int d = 0; d < 32; d++) {
            float4 w = sWd1s4[d * 16 + pp];
            float vv = (r & 2) ? ((r & 1) ? w.w : w.z) : ((r & 1) ? w.y : w.x);
            ce = fmaf(bg2[d], vv, ce);
        }
        scw[t] = make_float2(ce, Wd2[t * 3 + 1]);
    }
    __syncthreads();

    const int b = blockIdx.x * BLOCK + t;
    if (b >= nb) return;

    float* out_recon = out;
    float* out_lat   = out + (size_t)nb * 8;
    float* out_A     = out + (size_t)nb * 24;

    // ---------------- P0: load x ----------------
    u64 x2[4];
    {
        const float4* xp = (const float4*)(x + (size_t)b * 8);
        float4 a = xp[0], c = xp[1];
        x2[0] = pk(a.x, a.y); x2[1] = pk(a.z, a.w);
        x2[2] = pk(c.x, c.y); x2[3] = pk(c.z, c.w);
    }

    // ---------------- P1: encoder (staged weights, pre-dup pairs) -----------
    u64 l0p[4], l1p[4];
    #pragma unroll
    for (int q = 0; q < 4; q++) { l0p[q] = z2; l1p[q] = z2; }

    #pragma unroll 2
    for (int k = 0; k < 64; k++) {
        float4 wq = sencWq[k];
        float2 e1 = sencE1[k];
        float4 ca = sencC[2 * k];
        float4 cb = sencC[2 * k + 1];
        u64 w1d = pk(wq.x, wq.y), e0d = pk(wq.z, wq.w), e1d = pk(e1.x, e1.y);
        u64 c2[4] = { pk(ca.x, ca.y), pk(ca.z, ca.w),
                      pk(cb.x, cb.y), pk(cb.z, cb.w) };
        #pragma unroll
        for (int q = 0; q < 4; q++) {
            u64 h = relu2(fma2(x2[q], w1d, c2[q]));
            l0p[q] = fma2(h, e0d, l0p[q]);
            l1p[q] = fma2(h, e1d, l1p[q]);
        }
    }

    // ---------------- P2/P3: stats, noise, px/py, lat store ----------------
    float px[8], py[8];
    {
        float l0[8], l1[8];
        #pragma unroll
        for (int q = 0; q < 4; q++) {
            upk(l0p[q], l0[2 * q], l0[2 * q + 1]);
            upk(l1p[q], l1[2 * q], l1[2 * q + 1]);
        }
        float mu0 = 0.0f, mu1 = 0.0f;
        #pragma unroll
        for (int i = 0; i < 8; i++) { mu0 += l0[i]; mu1 += l1[i]; }
        mu0 *= 0.125f; mu1 *= 0.125f;

        float v0 = 0.0f, v1 = 0.0f;
        #pragma unroll
        for (int i = 0; i < 8; i++) {
            float c0 = l0[i] - mu0, c1 = l1[i] - mu1;
            v0 += c0 * c0; v1 += c1 * c1;
        }
        float sc0 = 3.0f / (sqrtf(v0 * (1.0f / 7.0f)) + 1e-8f);
        float sc1 = 3.0f / (sqrtf(v1 * (1.0f / 7.0f)) + 1e-8f);

        float nz[16];
        {
            const float4* np = (const float4*)(noise + (size_t)b * 16);
            float4 q0 = np[0], q1 = np[1], q2 = np[2], q3 = np[3];
            nz[0]=q0.x; nz[1]=q0.y; nz[2]=q0.z; nz[3]=q0.w;
            nz[4]=q1.x; nz[5]=q1.y; nz[6]=q1.z; nz[7]=q1.w;
            nz[8]=q2.x; nz[9]=q2.y; nz[10]=q2.z; nz[11]=q2.w;
            nz[12]=q3.x; nz[13]=q3.y; nz[14]=q3.z; nz[15]=q3.w;
        }
        #pragma unroll
        for (int i = 0; i < 8; i++) {
            px[i] = ((l0[i] - mu0) * sc0) + nz[2 * i]     * 0.05f;
            py[i] = ((l1[i] - mu1) * sc1) + nz[2 * i + 1] * 0.05f;
        }
        float4* lp = (float4*)(out_lat + (size_t)b * 16);
        #pragma unroll
        for (int q = 0; q < 4; q++) {
            float4 o;
            o.x = px[2 * q];     o.y = py[2 * q];
            o.z = px[2 * q + 1]; o.w = py[2 * q + 1];
            lp[q] = o;
        }
    }

    // ---------------- P4: Gabriel graph (expression-identical) ----------------
    unsigned am = 0;
    int deg[8];
    #pragma unroll
    for (int i = 0; i < 8; i++) deg[i] = 1;

    #pragma unroll
    for (int i = 0; i < 8; i++) {
        #pragma unroll
        for (int j = i + 1; j < 8; j++) {
            float mx = (px[i] + px[j]) * 0.5f;
            float my = (py[i] + py[j]) * 0.5f;
            float dx = px[i] - mx, dy = py[i] - my;
            float r2 = dx * dx + dy * dy;
            float mind2 = 3.402823e38f;
            #pragma unroll
            for (int k = 0; k < 8; k++) {
                if (k != i && k != j) {
                    float ax = px[k] - mx, ay = py[k] - my;
                    mind2 = fminf(mind2, ax * ax + ay * ay);
                }
            }
            if (mind2 >= r2) {
                am |= (1u << PIDX(i, j));
                deg[i]++; deg[j]++;
            }
        }
    }

    float dinv[8];
    #pragma unroll
    for (int i = 0; i < 8; i++) dinv[i] = rsqrtf((float)deg[i]);

    // ---------------- A output: warp-coalesced via bitmask shuffle ----------
    {
        const int lane = t & 31;
        const int m_  = lane & 15;
        const int ai_ = m_ >> 1;
        const int jb  = (m_ & 1) * 4;
        int sh[4];
        #pragma unroll
        for (int jj = 0; jj < 4; jj++) {
            int j = jb + jj;
            if (j == ai_) sh[jj] = 31;
            else {
                int lo = ai_ < j ? ai_ : j;
                int hi = ai_ < j ? j : ai_;
                sh[jj] = lo * 7 - (lo * (lo - 1)) / 2 + (hi - lo - 1);
            }
        }
        float4* warpA = (float4*)(out_A + (size_t)(blockIdx.x * BLOCK + (t & ~31)) * 64);
        #pragma unroll
        for (int k = 0; k < 16; k++) {
            unsigned a = __shfl_sync(0xffffffffu, am, 2 * k + (lane >> 4));
            float4 o;
            o.x = ((a >> sh[0]) & 1u) ? 1.0f : 0.0f;
            o.y = ((a >> sh[1]) & 1u) ? 1.0f : 0.0f;
            o.z = ((a >> sh[2]) & 1u) ? 1.0f : 0.0f;
            o.w = ((a >> sh[3]) & 1u) ? 1.0f : 0.0f;
            warpA[k * 32 + lane] = o;
        }
    }

    // ---------------- P5: qx/qy/s via wx = dinv*px (predicated adds) --------
    u64 qx2[4], qy2[4], s2[4];
    {
        float wx[8], wy[8];
        #pragma unroll
        for (int j = 0; j < 8; j++) {
            wx[j] = dinv[j] * px[j];
            wy[j] = dinv[j] * py[j];
        }

        float tqx = 0.0f, tqy = 0.0f, ts = 0.0f;
        #pragma unroll
        for (int n = 0; n < 8; n++) {
            float tx = wx[n], ty = wy[n], td = dinv[n];
            #pragma unroll
            for (int j = 0; j < 8; j++) {
                if (j == n) continue;
                int p = (n < j) ? PIDX(n, j) : PIDX(j, n);
                bool adj = (am >> p) & 1u;
                if (adj) { tx += wx[j]; ty += wy[j]; td += dinv[j]; }
            }
            float qxn = dinv[n] * tx;
            float qyn = dinv[n] * ty;
            float sn  = dinv[n] * td * 0.125f;
            if (n & 1) {
                qx2[n >> 1] = pk(tqx, qxn);
                qy2[n >> 1] = pk(tqy, qyn);
                s2[n >> 1]  = pk(ts, sn);
            } else {
                tqx = qxn; tqy = qyn; ts = sn;
            }
        }
    }

    // ---------------- P6: GCN channel values u_c (pre-dup Wg1 pairs) --------
    u64 u2[16];
    {
        float tu = 0.0f;
        #pragma unroll 2
        for (int c = 0; c < 32; c++) {
            float4 g   = sWg1q[c];
            float2 bgp = sWg1b[c];
            u64 g0d = pk(g.x, g.y), g1d = pk(g.z, g.w), bgd = pk(bgp.x, bgp.y);
            u64 acc2 = z2;
            #pragma unroll
            for (int q = 0; q < 4; q++) {
                u64 a = fma2(qx2[q], g0d, fma2(qy2[q], g1d, bgd));
                acc2 = fma2(s2[q], relu2(a), acc2);
            }
            float ua, ub; upk(acc2, ua, ub);
            float uc = ua + ub;
            if (c & 1) u2[c >> 1] = pk(tu, uc);
            else       tu = uc;
        }
    }

    // ---------------- P7: pair-split decoder, warp-rotated e order ----------
    float recon = sbd2v;
    {
        const int lane = t & 31;
        const bool lowq = (lane & 16) == 0;
        const int rot = (t >> 5) << 4;               // 0,16,32,48 per warp

        u64 uo[8], up_[8];
        #pragma unroll
        for (int k = 0; k < 8; k++) {
            uo[k]   = lowq ? u2[k]     : u2[k + 8];
            u64 snd = lowq ? u2[k + 8] : u2[k];
            up_[k]  = shflx_u64(snd, 16);
        }

        const int colbase = lowq ? 0 : 4;
        #pragma unroll 2
        for (int ee = 0; ee < 64; ee++) {
            int e = (ee + rot) & 63;
            const float4* wr = &sMT4[e * 8 + colbase];
            float4 f0 = wr[0], f1 = wr[1], f2 = wr[2], f3 = wr[3];
            u64 m0 = pk(f0.x, f0.y), m1 = pk(f0.z, f0.w);
            u64 m2 = pk(f1.x, f1.y), m3 = pk(f1.z, f1.w);
            u64 m4 = pk(f2.x, f2.y), m5 = pk(f2.z, f2.w);
            u64 m6 = pk(f3.x, f3.y), m7 = pk(f3.z, f3.w);

            u64 aA = fma2(uo[0], m0, z2); u64 aB = fma2(uo[1], m1, z2);
            aA = fma2(uo[2], m2, aA);     aB = fma2(uo[3], m3, aB);
            aA = fma2(uo[4], m4, aA);     aB = fma2(uo[5], m5, aB);
            aA = fma2(uo[6], m6, aA);     aB = fma2(uo[7], m7, aB);
            u64 ao = add2(aA, aB);
            float oa, ob; upk(ao, oa, ob);
            float p_own = oa + ob;

            u64 bA = fma2(up_[0], m0, z2); u64 bB = fma2(up_[1], m1, z2);
            bA = fma2(up_[2], m2, bA);     bB = fma2(up_[3], m3, bB);
            bA = fma2(up_[4], m4, bA);     bB = fma2(up_[5], m5, bB);
            bA = fma2(up_[6], m6, bA);     bB = fma2(up_[7], m7, bB);
            u64 bo = add2(bA, bB);
            float pa, pb; upk(bo, pa, pb);
            float p_oth = pa + pb;

            float p_rcv = __shfl_xor_sync(0xffffffffu, p_oth, 16);

            float2 cw = scw[e];
            float pre = (p_own + p_rcv) + cw.x;
            recon = fmaf(fmaxf(pre, 0.0f), cw.y, recon);
        }
    }

    {
        float4 r4 = {recon, recon, recon, recon};
        float4* rp = (float4*)(out_recon + (size_t)b * 8);
        rp[0] = r4;
        rp[1] = r4;
    }
}

extern "C" void kernel_launch(void* const* d_in, const int* in_sizes, int n_in,
                              void* d_out, int out_size)
{
    const float* x     = (const float*)d_in[0];
    const float* noise = (const float*)d_in[1];
    const float* We1   = (const float*)d_in[2];
    const float* be1   = (const float*)d_in[3];
    const float* We2   = (const float*)d_in[4];
    const float* be2   = (const float*)d_in[5];
    const float* Wg1   = (const float*)d_in[6];
    const float* bg1   = (const float*)d_in[7];
    const float* Wg2   = (const float*)d_in[8];
    const float* bg2   = (const float*)d_in[9];
    const float* Wd1   = (const float*)d_in[10];
    const float* bd1   = (const float*)d_in[11];
    const float* Wd2   = (const float*)d_in[12];
    const float* bd2   = (const float*)d_in[13];

    const int nb = in_sizes[0] / NN;
    float* out = (float*)d_out;

    dim3 grid((nb + BLOCK - 1) / BLOCK);
    gae_kernel<<<grid, BLOCK>>>(x, noise, We1, be1, We2, be2, Wg1, bg1,
                                Wg2, bg2, Wd1, bd1, Wd2, bd2, out, nb);
}

// round 14
// speedup vs baseline: 1.1628x; 1.0031x over previous
#include <cuda_runtime.h>
#include <cstdint>

// R14 = R13 with all f32x2 operands loaded DIRECTLY as 64-bit values
// (ulonglong2 / u64 shared-memory loads) instead of float4 + mov.b64 pk().
// Removes ~1200 ALU mov instructions per thread. Bit-identical outputs.
// Output layout: [recon (nb*8)] [lat (nb*16)] [A (nb*64)]

constexpr int NN = 8;
constexpr int BLOCK = 128;

using u64 = unsigned long long;

__device__ __forceinline__ u64 pk(float lo, float hi) {
    u64 r; asm("mov.b64 %0, {%1,%2};" : "=l"(r) : "f"(lo), "f"(hi)); return r;
}
__device__ __forceinline__ void upk(u64 v, float& lo, float& hi) {
    asm("mov.b64 {%0,%1}, %2;" : "=f"(lo), "=f"(hi) : "l"(v));
}
__device__ __forceinline__ u64 fma2(u64 a, u64 b, u64 c) {
    u64 d; asm("fma.rn.f32x2 %0, %1, %2, %3;" : "=l"(d) : "l"(a), "l"(b), "l"(c)); return d;
}
__device__ __forceinline__ u64 add2(u64 a, u64 b) {
    u64 d; asm("add.rn.f32x2 %0, %1, %2;" : "=l"(d) : "l"(a), "l"(b)); return d;
}
__device__ __forceinline__ u64 dup2(float v) { return pk(v, v); }
__device__ __forceinline__ u64 relu2(u64 v) {
    float a, b; upk(v, a, b);
    return pk(fmaxf(a, 0.0f), fmaxf(b, 0.0f));
}
__device__ __forceinline__ u64 shflx_u64(u64 v, int m) {
    float lo, hi; upk(v, lo, hi);
    lo = __shfl_xor_sync(0xffffffffu, lo, m);
    hi = __shfl_xor_sync(0xffffffffu, hi, m);
    return pk(lo, hi);
}

__device__ __forceinline__ constexpr int PIDX(int i, int j) { // i<j, 0..27
    return i * 7 - (i * (i - 1)) / 2 + (j - i - 1);
}

__global__ void __launch_bounds__(BLOCK, 7)
gae_kernel(const float* __restrict__ x, const float* __restrict__ noise,
           const float* __restrict__ We1, const float* __restrict__ be1,
           const float* __restrict__ We2, const float* __restrict__ be2,
           const float* __restrict__ Wg1, const float* __restrict__ bg1,
           const float* __restrict__ Wg2, const float* __restrict__ bg2,
           const float* __restrict__ Wd1, const float* __restrict__ bd1,
           const float* __restrict__ Wd2, const float* __restrict__ bd2,
           float* __restrict__ out, int nb)
{
    __shared__ float4 sencWq[64];       // (w1,w1, e0,e0) -> ull2 (w1d, e0d)
    __shared__ float2 sencE1[64];       // (e1,e1) -> u64 e1d
    __shared__ float4 sencC[128];       // [k][2]: c_i pairs -> ull2
    __shared__ float4 sWg1q[32];        // (g0,g0, g1,g1) -> ull2
    __shared__ float2 sWg1b[32];        // (bg,bg) -> u64
    __shared__ float4 sMT4[64 * 8];     // fused decoder M[e][c] -> ull2 pairs
    __shared__ float2 scw[64];          // (bg2@Wd1 + bd1, Wd2[e][1])
    __shared__ float  sbd2v;
    __shared__ float  sWg2T[32 * 33];   // Wg2 transposed, padded (staging)
    __shared__ float4 sWd1s4[32 * 16];  // Wd1 staged: [d][pp]

    const int t = threadIdx.x;
    const u64 z2 = pk(0.0f, 0.0f);

    // ---- stage raw weights ----
    if (t < 64) {
        float w1 = We1[64 + t];
        float w2 = We1[128 + t];
        float be = be1[t];
        float e0 = We2[2 * t], e1 = We2[2 * t + 1];
        sencWq[t] = make_float4(w1, w1, e0, e0);
        sencE1[t] = make_float2(e1, e1);
        float c[8];
        #pragma unroll
        for (int i = 0; i < 8; i++) c[i] = fmaf((float)i, w2, be);
        sencC[2 * t]     = make_float4(c[0], c[1], c[2], c[3]);
        sencC[2 * t + 1] = make_float4(c[4], c[5], c[6], c[7]);
    }
    if (t < 32) {
        float g0 = Wg1[t], g1 = Wg1[32 + t], bg = bg1[t];
        sWg1q[t] = make_float4(g0, g0, g1, g1);
        sWg1b[t] = make_float2(bg, bg);
    }
    for (int idx = t; idx < 1024; idx += BLOCK) {
        int c = idx >> 5, d = idx & 31;
        sWg2T[d * 33 + c] = Wg2[idx];
    }
    for (int idx = t; idx < 512; idx += BLOCK) {
        sWd1s4[idx] = *(const float4*)&Wd1[4 * idx];
    }
    if (t == 0) sbd2v = bd2[1];
    __syncthreads();

    // ---- fused decoder weights: M[e][c] = sum_d Wg2[c][d]*Wd1[d][e] ----
    {
        int c = t & 31, ep0 = t >> 5;
        u64 acc[8];
        #pragma unroll
        for (int k = 0; k < 8; k++) acc[k] = z2;
        #pragma unroll 2
        for (int d = 0; d < 32; d++) {
            u64 ad = dup2(sWg2T[d * 33 + c]);
            const ulonglong2* fb = (const ulonglong2*)&sWd1s4[d * 16 + ep0 * 4];
            ulonglong2 v0 = fb[0], v1 = fb[1], v2 = fb[2], v3 = fb[3];
            acc[0] = fma2(ad, v0.x, acc[0]);
            acc[1] = fma2(ad, v0.y, acc[1]);
            acc[2] = fma2(ad, v1.x, acc[2]);
            acc[3] = fma2(ad, v1.y, acc[3]);
            acc[4] = fma2(ad, v2.x, acc[4]);
            acc[5] = fma2(ad, v2.y, acc[5]);
            acc[6] = fma2(ad, v3.x, acc[6]);
            acc[7] = fma2(ad, v3.y, acc[7]);
        }
        #pragma unroll
        for (int k = 0; k < 8; k++) {
            int p = ep0 * 8 + k;
            float mlo, mhi; upk(acc[k], mlo, mhi);
            ((float*)sMT4)[(2 * p)     * 32 + c] = mlo;
            ((float*)sMT4)[(2 * p + 1) * 32 + c] = mhi;
        }
    }
    if (t < 64) {
        float ce = bd1[t];
        int pp = t >> 2, r = t & 3;
        #pragma unroll
        for (int d = 0; d < 32; d++) {
            float4 w = sWd1s4[d * 16 + pp];
            float vv = (r & 2) ? ((r & 1) ? w.w : w.z) : ((r & 1) ? w.y : w.x);
            ce = fmaf(bg2[d], vv, ce);
        }
        scw[t] = make_float2(ce, Wd2[t * 3 + 1]);
    }
    __syncthreads();

    const int b = blockIdx.x * BLOCK + t;
    if (b >= nb) return;

    float* out_recon = out;
    float* out_lat   = out + (size_t)nb * 8;
    float* out_A     = out + (size_t)nb * 24;

    // ---------------- P0: load x directly as 64-bit pairs ----------------
    u64 x2[4];
    {
        const ulonglong2* xp = (const ulonglong2*)(x + (size_t)b * 8);
        ulonglong2 xa = xp[0], xb = xp[1];
        x2[0] = xa.x; x2[1] = xa.y; x2[2] = xb.x; x2[3] = xb.y;
    }

    // ---------------- P1: encoder (direct 64-bit operand loads) -------------
    u64 l0p[4], l1p[4];
    #pragma unroll
    for (int q = 0; q < 4; q++) { l0p[q] = z2; l1p[q] = z2; }

    #pragma unroll 2
    for (int k = 0; k < 64; k++) {
        ulonglong2 wv = *(const ulonglong2*)&sencWq[k];
        u64 w1d = wv.x, e0d = wv.y;
        u64 e1d = ((const u64*)sencE1)[k];
        const ulonglong2* cc = (const ulonglong2*)&sencC[2 * k];
        ulonglong2 c01 = cc[0], c23 = cc[1];
        u64 c2[4] = { c01.x, c01.y, c23.x, c23.y };
        #pragma unroll
        for (int q = 0; q < 4; q++) {
            u64 h = relu2(fma2(x2[q], w1d, c2[q]));
            l0p[q] = fma2(h, e0d, l0p[q]);
            l1p[q] = fma2(h, e1d, l1p[q]);
        }
    }

    // ---------------- P2/P3: stats, noise, px/py, lat store ----------------
    float px[8], py[8];
    {
        float l0[8], l1[8];
        #pragma unroll
        for (int q = 0; q < 4; q++) {
            upk(l0p[q], l0[2 * q], l0[2 * q + 1]);
            upk(l1p[q], l1[2 * q], l1[2 * q + 1]);
        }
        float mu0 = 0.0f, mu1 = 0.0f;
        #pragma unroll
        for (int i = 0; i < 8; i++) { mu0 += l0[i]; mu1 += l1[i]; }
        mu0 *= 0.125f; mu1 *= 0.125f;

        float v0 = 0.0f, v1 = 0.0f;
        #pragma unroll
        for (int i = 0; i < 8; i++) {
            float c0 = l0[i] - mu0, c1 = l1[i] - mu1;
            v0 += c0 * c0; v1 += c1 * c1;
        }
        float sc0 = 3.0f / (sqrtf(v0 * (1.0f / 7.0f)) + 1e-8f);
        float sc1 = 3.0f / (sqrtf(v1 * (1.0f / 7.0f)) + 1e-8f);

        float nz[16];
        {
            const float4* np = (const float4*)(noise + (size_t)b * 16);
            float4 q0 = np[0], q1 = np[1], q2 = np[2], q3 = np[3];
            nz[0]=q0.x; nz[1]=q0.y; nz[2]=q0.z; nz[3]=q0.w;
            nz[4]=q1.x; nz[5]=q1.y; nz[6]=q1.z; nz[7]=q1.w;
            nz[8]=q2.x; nz[9]=q2.y; nz[10]=q2.z; nz[11]=q2.w;
            nz[12]=q3.x; nz[13]=q3.y; nz[14]=q3.z; nz[15]=q3.w;
        }
        #pragma unroll
        for (int i = 0; i < 8; i++) {
            px[i] = ((l0[i] - mu0) * sc0) + nz[2 * i]     * 0.05f;
            py[i] = ((l1[i] - mu1) * sc1) + nz[2 * i + 1] * 0.05f;
        }
        float4* lp = (float4*)(out_lat + (size_t)b * 16);
        #pragma unroll
        for (int q = 0; q < 4; q++) {
            float4 o;
            o.x = px[2 * q];     o.y = py[2 * q];
            o.z = px[2 * q + 1]; o.w = py[2 * q + 1];
            lp[q] = o;
        }
    }

    // ---------------- P4: Gabriel graph (expression-identical) ----------------
    unsigned am = 0;
    int deg[8];
    #pragma unroll
    for (int i = 0; i < 8; i++) deg[i] = 1;

    #pragma unroll
    for (int i = 0; i < 8; i++) {
        #pragma unroll
        for (int j = i + 1; j < 8; j++) {
            float mx = (px[i] + px[j]) * 0.5f;
            float my = (py[i] + py[j]) * 0.5f;
            float dx = px[i] - mx, dy = py[i] - my;
            float r2 = dx * dx + dy * dy;
            float mind2 = 3.402823e38f;
            #pragma unroll
            for (int k = 0; k < 8; k++) {
                if (k != i && k != j) {
                    float ax = px[k] - mx, ay = py[k] - my;
                    mind2 = fminf(mind2, ax * ax + ay * ay);
                }
            }
            if (mind2 >= r2) {
                am |= (1u << PIDX(i, j));
                deg[i]++; deg[j]++;
            }
        }
    }

    float dinv[8];
    #pragma unroll
    for (int i = 0; i < 8; i++) dinv[i] = rsqrtf((float)deg[i]);

    // ---------------- A output: warp-coalesced via bitmask shuffle ----------
    {
        const int lane = t & 31;
        const int m_  = lane & 15;
        const int ai_ = m_ >> 1;
        const int jb  = (m_ & 1) * 4;
        int sh[4];
        #pragma unroll
        for (int jj = 0; jj < 4; jj++) {
            int j = jb + jj;
            if (j == ai_) sh[jj] = 31;
            else {
                int lo = ai_ < j ? ai_ : j;
                int hi = ai_ < j ? j : ai_;
                sh[jj] = lo * 7 - (lo * (lo - 1)) / 2 + (hi - lo - 1);
            }
        }
        float4* warpA = (float4*)(out_A + (size_t)(blockIdx.x * BLOCK + (t & ~31)) * 64);
        #pragma unroll
        for (int k = 0; k < 16; k++) {
            unsigned a = __shfl_sync(0xffffffffu, am, 2 * k + (lane >> 4));
            float4 o;
            o.x = ((a >> sh[0]) & 1u) ? 1.0f : 0.0f;
            o.y = ((a >> sh[1]) & 1u) ? 1.0f : 0.0f;
            o.z = ((a >> sh[2]) & 1u) ? 1.0f : 0.0f;
            o.w = ((a >> sh[3]) & 1u) ? 1.0f : 0.0f;
            warpA[k * 32 + lane] = o;
        }
    }

    // ---------------- P5: qx/qy/s via wx = dinv*px (predicated adds) --------
    u64 qx2[4], qy2[4], s2[4];
    {
        float wx[8], wy[8];
        #pragma unroll
        for (int j = 0; j < 8; j++) {
            wx[j] = dinv[j] * px[j];
            wy[j] = dinv[j] * py[j];
        }

        float tqx = 0.0f, tqy = 0.0f, ts = 0.0f;
        #pragma unroll
        for (int n = 0; n < 8; n++) {
            float tx = wx[n], ty = wy[n], td = dinv[n];
            #pragma unroll
            for (int j = 0; j < 8; j++) {
                if (j == n) continue;
                int p = (n < j) ? PIDX(n, j) : PIDX(j, n);
                bool adj = (am >> p) & 1u;
                if (adj) { tx += wx[j]; ty += wy[j]; td += dinv[j]; }
            }
            float qxn = dinv[n] * tx;
            float qyn = dinv[n] * ty;
            float sn  = dinv[n] * td * 0.125f;
            if (n & 1) {
                qx2[n >> 1] = pk(tqx, qxn);
                qy2[n >> 1] = pk(tqy, qyn);
                s2[n >> 1]  = pk(ts, sn);
            } else {
                tqx = qxn; tqy = qyn; ts = sn;
            }
        }
    }

    // ---------------- P6: GCN channel values u_c (direct 64-bit loads) ------
    u64 u2[16];
    {
        float tu = 0.0f;
        #pragma unroll 2
        for (int c = 0; c < 32; c++) {
            ulonglong2 gv = *(const ulonglong2*)&sWg1q[c];
            u64 g0d = gv.x, g1d = gv.y;
            u64 bgd = ((const u64*)sWg1b)[c];
            u64 acc2 = z2;
            #pragma unroll
            for (int q = 0; q < 4; q++) {
                u64 a = fma2(qx2[q], g0d, fma2(qy2[q], g1d, bgd));
                acc2 = fma2(s2[q], relu2(a), acc2);
            }
            float ua, ub; upk(acc2, ua, ub);
            float uc = ua + ub;
            if (c & 1) u2[c >> 1] = pk(tu, uc);
            else       tu = uc;
        }
    }

    // ---------------- P7: pair-split decoder, direct 64-bit M loads ---------
    float recon = sbd2v;
    {
        const int lane = t & 31;
        const bool lowq = (lane & 16) == 0;
        const int rot = (t >> 5) << 4;               // 0,16,32,48 per warp

        u64 uo[8], up_[8];
        #pragma unroll
        for (int k = 0; k < 8; k++) {
            uo[k]   = lowq ? u2[k]     : u2[k + 8];
            u64 snd = lowq ? u2[k + 8] : u2[k];
            up_[k]  = shflx_u64(snd, 16);
        }

        const int colbase = lowq ? 0 : 4;
        #pragma unroll 2
        for (int ee = 0; ee < 64; ee++) {
            int e = (ee + rot) & 63;
            const ulonglong2* wr2 = (const ulonglong2*)&sMT4[e * 8 + colbase];
            ulonglong2 v0 = wr2[0], v1 = wr2[1], v2 = wr2[2], v3 = wr2[3];
            u64 m0 = v0.x, m1 = v0.y, m2 = v1.x, m3 = v1.y;
            u64 m4 = v2.x, m5 = v2.y, m6 = v3.x, m7 = v3.y;

            u64 aA = fma2(uo[0], m0, z2); u64 aB = fma2(uo[1], m1, z2);
            aA = fma2(uo[2], m2, aA);     aB = fma2(uo[3], m3, aB);
            aA = fma2(uo[4], m4, aA);     aB = fma2(uo[5], m5, aB);
            aA = fma2(uo[6], m6, aA);     aB = fma2(uo[7], m7, aB);
            u64 ao = add2(aA, aB);
            float oa, ob; upk(ao, oa, ob);
            float p_own = oa + ob;

            u64 bA = fma2(up_[0], m0, z2); u64 bB = fma2(up_[1], m1, z2);
            bA = fma2(up_[2], m2, bA);     bB = fma2(up_[3], m3, bB);
            bA = fma2(up_[4], m4, bA);     bB = fma2(up_[5], m5, bB);
            bA = fma2(up_[6], m6, bA);     bB = fma2(up_[7], m7, bB);
            u64 bo = add2(bA, bB);
            float pa, pb; upk(bo, pa, pb);
            float p_oth = pa + pb;

            float p_rcv = __shfl_xor_sync(0xffffffffu, p_oth, 16);

            float2 cw = scw[e];
            float pre = (p_own + p_rcv) + cw.x;
            recon = fmaf(fmaxf(pre, 0.0f), cw.y, recon);
        }
    }

    {
        float4 r4 = {recon, recon, recon, recon};
        float4* rp = (float4*)(out_recon + (size_t)b * 8);
        rp[0] = r4;
        rp[1] = r4;
    }
}

extern "C" void kernel_launch(void* const* d_in, const int* in_sizes, int n_in,
                              void* d_out, int out_size)
{
    const float* x     = (const float*)d_in[0];
    const float* noise = (const float*)d_in[1];
    const float* We1   = (const float*)d_in[2];
    const float* be1   = (const float*)d_in[3];
    const float* We2   = (const float*)d_in[4];
    const float* be2   = (const float*)d_in[5];
    const float* Wg1   = (const float*)d_in[6];
    const float* bg1   = (const float*)d_in[7];
    const float* Wg2   = (const float*)d_in[8];
    const float* bg2   = (const float*)d_in[9];
    const float* Wd1   = (const float*)d_in[10];
    const float* bd1   = (const float*)d_in[11];
    const float* Wd2   = (const float*)d_in[12];
    const float* bd2   = (const float*)d_in[13];

    const int nb = in_sizes[0] / NN;
    float* out = (float*)d_out;

    dim3 grid((nb + BLOCK - 1) / BLOCK);
    gae_kernel<<<grid, BLOCK>>>(x, noise, We1, be1, We2, be2, Wg1, bg1,
                                Wg2, bg2, Wd1, bd1, Wd2, bd2, out, nb);
}